// round 12
// baseline (speedup 1.0000x reference)
#include <cuda_runtime.h>
#include <cstdint>
#include <cstddef>

#define BS 4
#define NF 8
#define NT 256
#define DIN 64
#define NH 8
#define DOUT 64
#define BF (BS*NF)          // 32
#define NK (NH*DIN)         // 512

// Scratch (allocation-free)
__device__ float g_Q[BF * NT * NH * 2];               // [bf][t][h][e]
__device__ float g_K[BF * NT * NH * 2];
__device__ float4 g_K2[BF * 4 * NT];                  // [bf][hp][l]
__device__ unsigned g_Xt[(size_t)BF * DIN * NT];      // tf32 bits, [bf][d][phys(l)]
__device__ unsigned g_Wt[(size_t)NF * DOUT * NK];     // tf32 bits, [f][o][phys(k)]

static __device__ __forceinline__ unsigned f2tf32(float v) {
    unsigned t; asm("cvt.rna.tf32.f32 %0, %1;" : "=r"(t) : "f"(v)); return t;
}
#define PAIR_BAR(p)  asm volatile("bar.sync %0, 64;" :: "r"(1 + (p)) : "memory")

static __device__ __forceinline__ void mma8(float* d, unsigned a0, unsigned a1,
                                            unsigned a2, unsigned a3,
                                            unsigned b0, unsigned b1) {
    asm volatile("mma.sync.aligned.m16n8k8.row.col.f32.tf32.tf32.f32 "
        "{%0,%1,%2,%3}, {%4,%5,%6,%7}, {%8,%9}, {%0,%1,%2,%3};"
        : "+f"(d[0]), "+f"(d[1]), "+f"(d[2]), "+f"(d[3])
        : "r"(a0), "r"(a1), "r"(a2), "r"(a3), "r"(b0), "r"(b1));
}

static __device__ __forceinline__ float warp_max_f32(float x) {
    unsigned b = __float_as_uint(x);
    unsigned e = b ^ (unsigned)(((int)b >> 31) | 0x80000000);
    unsigned r;
    asm volatile("redux.sync.max.u32 %0, %1, 0xffffffff;" : "=r"(r) : "r"(e));
    unsigned bb = ((int)r < 0) ? (r ^ 0x80000000u) : ~r;
    return __uint_as_float(bb);
}

// ---------------------------------------------------------------------------
// Fused pre-kernel (unchanged): [0,1024) QK (+g_K2); X->Xt; W->Wt.
// phys(k) = (k&~7) + 2*(k&3) + ((k>>2)&1)
// ---------------------------------------------------------------------------
#define QK_BLOCKS 1024
#define XT_BLOCKS 128
#define WT_BLOCKS 64

__global__ void __launch_bounds__(256)
pre_kernel(const float* __restrict__ X,
           const float* __restrict__ Wq,
           const float* __restrict__ Wk,
           const float* __restrict__ W)
{
    extern __shared__ float tsm[];   // [64][65]
    int tid = threadIdx.x;

    if (blockIdx.x < QK_BLOCKS) {
        int idx  = blockIdx.x * 8 + (tid >> 5);
        int lane = tid & 31;
        int t_ft = idx & (NF * NT - 1);

        const float* x = X + (size_t)idx * DIN;
        float x0 = __ldg(&x[lane]);
        float x1 = __ldg(&x[lane + 32]);

        int dq = lane >> 2;
        const float4* Wq4 = (const float4*)(Wq + (size_t)t_ft * (DIN * 16));
        const float4* Wk4 = (const float4*)(Wk + (size_t)t_ft * (DIN * 16));

        float4 wq[8], wk[8];
#pragma unroll
        for (int i = 0; i < 8; i++) {
            wq[i] = __ldg(&Wq4[i * 32 + lane]);
            wk[i] = __ldg(&Wk4[i * 32 + lane]);
        }
        float4 aq = {0,0,0,0}, ak = {0,0,0,0};
#pragma unroll
        for (int i = 0; i < 8; i++) {
            int dsel = (i & 3) * 8 + dq;
            float xv = __shfl_sync(0xffffffffu, (i < 4) ? x0 : x1, dsel);
            aq.x = fmaf(xv, wq[i].x, aq.x); aq.y = fmaf(xv, wq[i].y, aq.y);
            aq.z = fmaf(xv, wq[i].z, aq.z); aq.w = fmaf(xv, wq[i].w, aq.w);
            ak.x = fmaf(xv, wk[i].x, ak.x); ak.y = fmaf(xv, wk[i].y, ak.y);
            ak.z = fmaf(xv, wk[i].z, ak.z); ak.w = fmaf(xv, wk[i].w, ak.w);
        }
#pragma unroll
        for (int off = 16; off >= 4; off >>= 1) {
            aq.x += __shfl_xor_sync(0xffffffffu, aq.x, off);
            aq.y += __shfl_xor_sync(0xffffffffu, aq.y, off);
            aq.z += __shfl_xor_sync(0xffffffffu, aq.z, off);
            aq.w += __shfl_xor_sync(0xffffffffu, aq.w, off);
            ak.x += __shfl_xor_sync(0xffffffffu, ak.x, off);
            ak.y += __shfl_xor_sync(0xffffffffu, ak.y, off);
            ak.z += __shfl_xor_sync(0xffffffffu, ak.z, off);
            ak.w += __shfl_xor_sync(0xffffffffu, ak.w, off);
        }
        if (lane < 4) {
            *(float4*)(g_Q + (size_t)idx * 16 + lane * 4) = aq;
        } else if (lane < 8) {
            *(float4*)(g_K + (size_t)idx * 16 + (lane - 4) * 4) = ak;
            int hp = lane - 4;
            g_K2[((size_t)(idx >> 8) * 4 + hp) * NT + (idx & 255)] = ak;
        }
    }
    else if (blockIdx.x < QK_BLOCKS + XT_BLOCKS) {
        int b  = blockIdx.x - QK_BLOCKS;
        int bf = b >> 2, lc = b & 3;
        const float4* src = (const float4*)(X + ((size_t)bf * NT + lc * 64) * DIN);
        for (int i = tid; i < 64 * 16; i += 256) {
            int r = i >> 4, c0 = (i & 15) * 4;
            float4 v = __ldg(&src[i]);
            tsm[r * 65 + c0 + 0] = v.x;
            tsm[r * 65 + c0 + 1] = v.y;
            tsm[r * 65 + c0 + 2] = v.z;
            tsm[r * 65 + c0 + 3] = v.w;
        }
        __syncthreads();
        unsigned* dst = g_Xt + (size_t)bf * (DIN * NT) + lc * 64;
        for (int i = tid; i < 64 * 32; i += 256) {
            int d = i >> 5, p = i & 31;
            int g8 = p >> 2, s = p & 3;
            int la = g8 * 8 + s, lb = la + 4;
            uint2 o;
            o.x = f2tf32(tsm[la * 65 + d]);
            o.y = f2tf32(tsm[lb * 65 + d]);
            *(uint2*)(dst + (size_t)d * NT + g8 * 8 + 2 * s) = o;
        }
    }
    else {
        int b  = blockIdx.x - QK_BLOCKS - XT_BLOCKS;
        int f = b >> 3, kc = b & 7;
        const float4* src = (const float4*)(W + ((size_t)f * NK + kc * 64) * DOUT);
        for (int i = tid; i < 64 * 16; i += 256) {
            int r = i >> 4, c0 = (i & 15) * 4;
            float4 v = __ldg(&src[i]);
            tsm[r * 65 + c0 + 0] = v.x;
            tsm[r * 65 + c0 + 1] = v.y;
            tsm[r * 65 + c0 + 2] = v.z;
            tsm[r * 65 + c0 + 3] = v.w;
        }
        __syncthreads();
        unsigned* dst = g_Wt + (size_t)f * (DOUT * NK) + kc * 64;
        for (int i = tid; i < 64 * 32; i += 256) {
            int o = i >> 5, p = i & 31;
            int g8 = p >> 2, s = p & 3;
            int ka = g8 * 8 + s, kb = ka + 4;
            uint2 ov;
            ov.x = f2tf32(tsm[ka * 65 + o]);
            ov.y = f2tf32(tsm[kb * 65 + o]);
            *(uint2*)(dst + (size_t)o * NK + g8 * 8 + 2 * s) = ov;
        }
    }
}

// ---------------------------------------------------------------------------
// FUSED attn, 8-t blocks, 3 blocks/SM target.  grid = BF*32 = 1024, 256 thr.
// smem: P[64][264] | invsm[64]  = 67840 B.  No Xt tile: MMA1-B from L2 g_Xt.
// Av overlays pair's P region after pair-local MMA1.
// ---------------------------------------------------------------------------
#define SP 264
#define INV_OFF (64*SP)              // 16896
#define K2_BYTES ((INV_OFF + 64)*4)  // 67840

// Av row address (word offset in Pb): pair region + parity slot + bank skew
static __device__ __forceinline__ int av_off(int t) {
    return (t >> 1) * (16 * SP) + (t & 1) * 520 + ((t >> 1) & 1) * 16;
}

__global__ void __launch_bounds__(256, 3)
attn_kernel(const float* __restrict__ ac,
            const float* __restrict__ alpha,
            const float* __restrict__ wkey,
            const float* __restrict__ u,
            const float* __restrict__ Bv,
            float* __restrict__ Out)
{
    extern __shared__ float sm[];
    unsigned* Pb  = (unsigned*)sm;            // [64][SP] tf32 bits (phys cols)
    float* invsm = sm + INV_OFF;              // [64]

    int bf   = blockIdx.x >> 5;
    int f    = bf & (NF - 1);
    int t0   = (blockIdx.x & 31) << 3;
    int tid  = threadIdx.x;
    int lane = tid & 31;
    int w    = tid >> 5;                      // 8 warps
    int pair = w >> 1;

    int t     = t0 + w;
    int idx_t = bf * NT + t;
    float alpha_f = __ldg(&alpha[f]);
    float a0c = __ldg(&wkey[f*4+0]), b0c = __ldg(&wkey[f*4+1]);
    float a1c = __ldg(&wkey[f*4+2]), b1c = __ldg(&wkey[f*4+3]);
    float v0 = -alpha_f;
    float rbase = (float)(lane - t);
    int pbase = (lane & ~7) + 2 * (lane & 3) + ((lane >> 2) & 1);
    const float* uf = u + (size_t)f * (NT * 2);

    // ---- scores + softmax (K from L2 g_K2, u from L2; raw exp stored) ----
#pragma unroll
    for (int hp = 0; hp < 4; hp++) {
        int h0 = hp * 2;
        float4 q4 = __ldg((const float4*)(g_Q + (size_t)idx_t * 16 + h0 * 2));
        float4 k4 = __ldg((const float4*)(g_K + (size_t)idx_t * 16 + h0 * 2));
        float v1a = 2.0f * alpha_f * __ldg(&ac[f * NH + h0]);
        float v1b = 2.0f * alpha_f * __ldg(&ac[f * NH + h0 + 1]);
        float qa0 = q4.x + v0, qa1 = q4.y + v1a;
        float A0 = fmaf(qa0, a0c, qa1 * a1c), B0 = fmaf(qa0, b0c, qa1 * b1c);
        float qb0 = q4.z + v0, qb1 = q4.w + v1b;
        float A1 = fmaf(qb0, a0c, qb1 * a1c), B1 = fmaf(qb0, b0c, qb1 * b1c);

        const float4* Kh = g_K2 + ((size_t)bf * 4 + hp) * NT;
        float s0[8], s1[8], m0 = -3.4e38f, m1 = -3.4e38f;
#pragma unroll
        for (int half = 0; half < 2; half++) {
            float4 kv[4];
            float2 uvv[4];
#pragma unroll
            for (int j2 = 0; j2 < 4; j2++) {
                int j = half * 4 + j2;
                kv[j2] = __ldg(&Kh[j * 32 + lane]);
                uvv[j2] = __ldg((const float2*)(uf + (j * 32 + lane) * 2));
            }
#pragma unroll
            for (int j2 = 0; j2 < 4; j2++) {
                int j = half * 4 + j2;
                float r = rbase + 32.0f * j;
                float ut0 = fmaf(uvv[j2].x, k4.x, uvv[j2].y * k4.y);
                float ut1 = fmaf(uvv[j2].x, k4.z, uvv[j2].y * k4.w);
                float base0 = fmaf(r, fmaf(A0, r, B0), ut0);
                float base1 = fmaf(r, fmaf(A1, r, B1), ut1);
                base0 = fmaf(q4.x, kv[j2].x, base0); base0 = fmaf(q4.y, kv[j2].y, base0);
                base1 = fmaf(q4.z, kv[j2].z, base1); base1 = fmaf(q4.w, kv[j2].w, base1);
                s0[j] = base0; s1[j] = base1;
                m0 = fmaxf(m0, base0); m1 = fmaxf(m1, base1);
            }
        }
        m0 = warp_max_f32(m0);
        m1 = warp_max_f32(m1);

        unsigned* pr0 = Pb + (8 * w + h0) * SP;
        float sum0 = 0.f, sum1 = 0.f;
#pragma unroll
        for (int j = 0; j < 8; j++) {
            float e0 = __expf(s0[j] - m0);
            float e1 = __expf(s1[j] - m1);
            pr0[j * 32 + pbase]      = f2tf32(e0);
            pr0[SP + j * 32 + pbase] = f2tf32(e1);
            sum0 += e0; sum1 += e1;
        }
#pragma unroll
        for (int o = 16; o; o >>= 1) {
            sum0 += __shfl_xor_sync(0xffffffffu, sum0, o);
            sum1 += __shfl_xor_sync(0xffffffffu, sum1, o);
        }
        if (lane == 0) {
            invsm[8 * w + h0]     = 1.0f / sum0;
            invsm[8 * w + h0 + 1] = 1.0f / sum1;
        }
    }
    PAIR_BAR(pair);    // pair's 16 P rows + invs ready

    // ---- MMA1 (pair-local A, B from L2): warp = pair's m16, d-half (w&1) ----
    int g  = lane >> 2;
    int s4 = lane & 3;
    int n0 = (w & 1) * 32;

    const uint2* aR0 = (const uint2*)(Pb + (16 * pair + g) * SP) + s4;
    const uint2* aR1 = (const uint2*)(Pb + (16 * pair + g + 8) * SP) + s4;
    const uint2* xb = (const uint2*)(g_Xt + (size_t)bf * DIN * NT);
    const uint2* bG0 = xb + (size_t)(n0 + 0 + g) * (NT / 2) + s4;
    const uint2* bG1 = xb + (size_t)(n0 + 8 + g) * (NT / 2) + s4;
    const uint2* bG2 = xb + (size_t)(n0 + 16 + g) * (NT / 2) + s4;
    const uint2* bG3 = xb + (size_t)(n0 + 24 + g) * (NT / 2) + s4;

    float acc[4][4];
#pragma unroll
    for (int i = 0; i < 4; i++)
#pragma unroll
        for (int j = 0; j < 4; j++) acc[i][j] = 0.f;

#pragma unroll
    for (int k0 = 0; k0 < 256; k0 += 8) {
        int ki = k0 >> 1;
        uint2 a02 = aR0[ki], a13 = aR1[ki];
        uint2 b0 = __ldg(&bG0[ki]);
        uint2 b1 = __ldg(&bG1[ki]);
        uint2 b2 = __ldg(&bG2[ki]);
        uint2 b3 = __ldg(&bG3[ki]);
        mma8(acc[0], a02.x, a13.x, a02.y, a13.y, b0.x, b0.y);
        mma8(acc[1], a02.x, a13.x, a02.y, a13.y, b1.x, b1.y);
        mma8(acc[2], a02.x, a13.x, a02.y, a13.y, b2.x, b2.y);
        mma8(acc[3], a02.x, a13.x, a02.y, a13.y, b3.x, b3.y);
    }

    int thA = 16 * pair + g, thB = thA + 8;
    float invA = invsm[thA], invB = invsm[thB];
    PAIR_BAR(pair);    // pair's P rows fully consumed -> reuse as Av

    // ---- Av (normalized vals tf32) into pair's own P region ----
    {
        int tA = thA >> 3, hA = thA & 7;   // tA = 2*pair, tB = 2*pair+1
        int tB = thB >> 3, hB = thB & 7;
        int j = 2 * s4;
        int p0 = 2 * (j & 3) + ((j >> 2) & 1);
        int p1 = 2 * ((j + 1) & 3) + (((j + 1) >> 2) & 1);
        unsigned* avA = Pb + av_off(tA);
        unsigned* avB = Pb + av_off(tB);
#pragma unroll
        for (int nt = 0; nt < 4; nt++) {
            int kbaseA = hA * 64 + ((n0 + 8 * nt + 2 * s4) & ~7);
            int kbaseB = hB * 64 + ((n0 + 8 * nt + 2 * s4) & ~7);
            avA[kbaseA + p0] = f2tf32(acc[nt][0] * invA);
            avA[kbaseA + p1] = f2tf32(acc[nt][1] * invA);
            avB[kbaseB + p0] = f2tf32(acc[nt][2] * invB);
            avB[kbaseB + p1] = f2tf32(acc[nt][3] * invB);
        }
    }
    __syncthreads();   // all pairs' Av ready

    // ---- MMA2: Out[8 t][64 o] = Av @ Wt^T + b.  8 warps, n-split 8, K=512.
    // A rows 8..15 alias row g (outputs discarded). Two acc chains (k halves).
    int n0b = 8 * w;
    float acc2a[4] = {0.f, 0.f, 0.f, 0.f};
    float acc2b[4] = {0.f, 0.f, 0.f, 0.f};
    const uint2* aP0 = (const uint2*)(Pb + av_off(g)) + s4;
    const uint2* wR  = (const uint2*)(g_Wt + (size_t)f * DOUT * NK + (size_t)(n0b + g) * NK) + s4;
#pragma unroll
    for (int k0 = 0; k0 < 256; k0 += 8) {
        int ki = k0 >> 1;
        uint2 a02 = aP0[ki];
        uint2 b01 = __ldg(&wR[ki]);
        mma8(acc2a, a02.x, a02.x, a02.y, a02.y, b01.x, b01.y);
        uint2 c02 = aP0[ki + 128];
        uint2 d01 = __ldg(&wR[ki + 128]);
        mma8(acc2b, c02.x, c02.x, c02.y, c02.y, d01.x, d01.y);
    }

    {
        int tt = t0 + g;
        int oc = n0b + 2 * s4;
        float2 ba = __ldg((const float2*)(Bv + ((size_t)(f * NT + tt)) * DOUT + oc));
        float2 r;
        r.x = acc2a[0] + acc2b[0] + ba.x;
        r.y = acc2a[1] + acc2b[1] + ba.y;
        *(float2*)(Out + ((size_t)(bf * NT + tt)) * DOUT + oc) = r;
    }
}

// ---------------------------------------------------------------------------
extern "C" void kernel_launch(void* const* d_in, const int* in_sizes, int n_in,
                              void* d_out, int out_size)
{
    const float* X     = (const float*)d_in[0];
    const float* ac    = (const float*)d_in[1];
    const float* alpha = (const float*)d_in[2];
    const float* Wq    = (const float*)d_in[3];
    const float* Wk    = (const float*)d_in[4];
    const float* wkey  = (const float*)d_in[5];
    const float* u     = (const float*)d_in[6];
    const float* W     = (const float*)d_in[7];
    const float* Bv    = (const float*)d_in[8];
    float* Out = (float*)d_out;

    cudaFuncSetAttribute(attn_kernel, cudaFuncAttributeMaxDynamicSharedMemorySize, K2_BYTES);

    pre_kernel<<<QK_BLOCKS + XT_BLOCKS + WT_BLOCKS, 256, 64 * 65 * 4>>>(X, Wq, Wk, W);
    attn_kernel<<<BF * 32, 256, K2_BYTES>>>(ac, alpha, wkey, u, Bv, Out);
}

// round 14
// speedup vs baseline: 1.3024x; 1.3024x over previous
#include <cuda_runtime.h>
#include <cstdint>
#include <cstddef>

#define BS 4
#define NF 8
#define NT 256
#define DIN 64
#define NH 8
#define DOUT 64
#define BF (BS*NF)          // 32
#define NK (NH*DIN)         // 512

// Scratch (allocation-free)
__device__ float g_Q[BF * NT * NH * 2];               // [bf][t][h][e]
__device__ float g_K[BF * NT * NH * 2];
__device__ float4 g_K2[BF * 4 * NT];                  // [bf][hp][l]
__device__ unsigned g_Xt[(size_t)BF * DIN * NT];      // tf32 bits, [bf][d][phys(l)]
__device__ unsigned g_Wt[(size_t)NF * DOUT * NK];     // tf32 bits, [f][o][phys(k)]

static __device__ __forceinline__ unsigned f2tf32(float v) {
    unsigned t; asm("cvt.rna.tf32.f32 %0, %1;" : "=r"(t) : "f"(v)); return t;
}
static __device__ __forceinline__ uint32_t smem_u32(const void* p) {
    uint32_t a;
    asm("{ .reg .u64 t; cvta.to.shared.u64 t, %1; cvt.u32.u64 %0, t; }" : "=r"(a) : "l"(p));
    return a;
}
#define CP_ASYNC16(dst, src) \
    asm volatile("cp.async.cg.shared.global [%0], [%1], 16;" :: "r"(dst), "l"(src) : "memory")
#define CP_COMMIT()  asm volatile("cp.async.commit_group;" ::: "memory")
#define CP_WAIT0()   asm volatile("cp.async.wait_group 0;" ::: "memory")
#define BAR_ARRIVE(id, n) asm volatile("bar.arrive %0, %1;" :: "r"(id), "r"(n) : "memory")
#define BAR_SYNC(id, n)   asm volatile("bar.sync %0, %1;"   :: "r"(id), "r"(n) : "memory")

static __device__ __forceinline__ void mma8(float* d, unsigned a0, unsigned a1,
                                            unsigned a2, unsigned a3,
                                            unsigned b0, unsigned b1) {
    asm volatile("mma.sync.aligned.m16n8k8.row.col.f32.tf32.tf32.f32 "
        "{%0,%1,%2,%3}, {%4,%5,%6,%7}, {%8,%9}, {%0,%1,%2,%3};"
        : "+f"(d[0]), "+f"(d[1]), "+f"(d[2]), "+f"(d[3])
        : "r"(a0), "r"(a1), "r"(a2), "r"(a3), "r"(b0), "r"(b1));
}

static __device__ __forceinline__ float warp_max_f32(float x) {
    unsigned b = __float_as_uint(x);
    unsigned e = b ^ (unsigned)(((int)b >> 31) | 0x80000000);
    unsigned r;
    asm volatile("redux.sync.max.u32 %0, %1, 0xffffffff;" : "=r"(r) : "r"(e));
    unsigned bb = ((int)r < 0) ? (r ^ 0x80000000u) : ~r;
    return __uint_as_float(bb);
}

// ---------------------------------------------------------------------------
// Fused pre-kernel (unchanged): [0,1024) QK (+g_K2); X->Xt; W->Wt.
// phys(k) = (k&~7) + 2*(k&3) + ((k>>2)&1)
// ---------------------------------------------------------------------------
#define QK_BLOCKS 1024
#define XT_BLOCKS 128
#define WT_BLOCKS 64

__global__ void __launch_bounds__(256)
pre_kernel(const float* __restrict__ X,
           const float* __restrict__ Wq,
           const float* __restrict__ Wk,
           const float* __restrict__ W)
{
    extern __shared__ float tsm[];   // [64][65]
    int tid = threadIdx.x;

    if (blockIdx.x < QK_BLOCKS) {
        int idx  = blockIdx.x * 8 + (tid >> 5);
        int lane = tid & 31;
        int t_ft = idx & (NF * NT - 1);

        const float* x = X + (size_t)idx * DIN;
        float x0 = __ldg(&x[lane]);
        float x1 = __ldg(&x[lane + 32]);

        int dq = lane >> 2;
        const float4* Wq4 = (const float4*)(Wq + (size_t)t_ft * (DIN * 16));
        const float4* Wk4 = (const float4*)(Wk + (size_t)t_ft * (DIN * 16));

        float4 wq[8], wk[8];
#pragma unroll
        for (int i = 0; i < 8; i++) {
            wq[i] = __ldg(&Wq4[i * 32 + lane]);
            wk[i] = __ldg(&Wk4[i * 32 + lane]);
        }
        float4 aq = {0,0,0,0}, ak = {0,0,0,0};
#pragma unroll
        for (int i = 0; i < 8; i++) {
            int dsel = (i & 3) * 8 + dq;
            float xv = __shfl_sync(0xffffffffu, (i < 4) ? x0 : x1, dsel);
            aq.x = fmaf(xv, wq[i].x, aq.x); aq.y = fmaf(xv, wq[i].y, aq.y);
            aq.z = fmaf(xv, wq[i].z, aq.z); aq.w = fmaf(xv, wq[i].w, aq.w);
            ak.x = fmaf(xv, wk[i].x, ak.x); ak.y = fmaf(xv, wk[i].y, ak.y);
            ak.z = fmaf(xv, wk[i].z, ak.z); ak.w = fmaf(xv, wk[i].w, ak.w);
        }
#pragma unroll
        for (int off = 16; off >= 4; off >>= 1) {
            aq.x += __shfl_xor_sync(0xffffffffu, aq.x, off);
            aq.y += __shfl_xor_sync(0xffffffffu, aq.y, off);
            aq.z += __shfl_xor_sync(0xffffffffu, aq.z, off);
            aq.w += __shfl_xor_sync(0xffffffffu, aq.w, off);
            ak.x += __shfl_xor_sync(0xffffffffu, ak.x, off);
            ak.y += __shfl_xor_sync(0xffffffffu, ak.y, off);
            ak.z += __shfl_xor_sync(0xffffffffu, ak.z, off);
            ak.w += __shfl_xor_sync(0xffffffffu, ak.w, off);
        }
        if (lane < 4) {
            *(float4*)(g_Q + (size_t)idx * 16 + lane * 4) = aq;
        } else if (lane < 8) {
            *(float4*)(g_K + (size_t)idx * 16 + (lane - 4) * 4) = ak;
            int hp = lane - 4;
            g_K2[((size_t)(idx >> 8) * 4 + hp) * NT + (idx & 255)] = ak;
        }
    }
    else if (blockIdx.x < QK_BLOCKS + XT_BLOCKS) {
        int b  = blockIdx.x - QK_BLOCKS;
        int bf = b >> 2, lc = b & 3;
        const float4* src = (const float4*)(X + ((size_t)bf * NT + lc * 64) * DIN);
        for (int i = tid; i < 64 * 16; i += 256) {
            int r = i >> 4, c0 = (i & 15) * 4;
            float4 v = __ldg(&src[i]);
            tsm[r * 65 + c0 + 0] = v.x;
            tsm[r * 65 + c0 + 1] = v.y;
            tsm[r * 65 + c0 + 2] = v.z;
            tsm[r * 65 + c0 + 3] = v.w;
        }
        __syncthreads();
        unsigned* dst = g_Xt + (size_t)bf * (DIN * NT) + lc * 64;
        for (int i = tid; i < 64 * 32; i += 256) {
            int d = i >> 5, p = i & 31;
            int g8 = p >> 2, s = p & 3;
            int la = g8 * 8 + s, lb = la + 4;
            uint2 o;
            o.x = f2tf32(tsm[la * 65 + d]);
            o.y = f2tf32(tsm[lb * 65 + d]);
            *(uint2*)(dst + (size_t)d * NT + g8 * 8 + 2 * s) = o;
        }
    }
    else {
        int b  = blockIdx.x - QK_BLOCKS - XT_BLOCKS;
        int f = b >> 3, kc = b & 7;
        const float4* src = (const float4*)(W + ((size_t)f * NK + kc * 64) * DOUT);
        for (int i = tid; i < 64 * 16; i += 256) {
            int r = i >> 4, c0 = (i & 15) * 4;
            float4 v = __ldg(&src[i]);
            tsm[r * 65 + c0 + 0] = v.x;
            tsm[r * 65 + c0 + 1] = v.y;
            tsm[r * 65 + c0 + 2] = v.z;
            tsm[r * 65 + c0 + 3] = v.w;
        }
        __syncthreads();
        unsigned* dst = g_Wt + (size_t)f * (DOUT * NK) + kc * 64;
        for (int i = tid; i < 64 * 32; i += 256) {
            int o = i >> 5, p = i & 31;
            int g8 = p >> 2, s = p & 3;
            int ka = g8 * 8 + s, kb = ka + 4;
            uint2 ov;
            ov.x = f2tf32(tsm[ka * 65 + o]);
            ov.y = f2tf32(tsm[kb * 65 + o]);
            *(uint2*)(dst + (size_t)o * NK + g8 * 8 + 2 * s) = ov;
        }
    }
}

// ---------------------------------------------------------------------------
// FUSED attn, m32n32k2 MMA1 retile + quad arrive/sync decoupling.
// grid = BF*16 = 512, 512 threads.
// smem words: P[128][264] | Xt[64][264] | invsm[128]  -> 203264 B
// Quad q's P region (rows 32q..32q+31, 8448 words) is reused after its MMA1:
//   [0, 2208): Av rows t=4q..4q+3 (stride 552, +68/h-group skew)
//   [2560, 4608): k-split partial accumulators
// red[1024] overlays Xtb for MMA2 k-reduction (after block sync).
// ---------------------------------------------------------------------------
#define SP 264
#define QREG (32*SP)                 // 8448 words per quad region
#define XT_OFF (128*SP)              // 33792
#define INV_OFF (XT_OFF + 64*SP)     // 50688
#define K2_BYTES ((INV_OFF + 128)*4) // 203264

// Av word offset of row t
static __device__ __forceinline__ int av_base(int t) {
    return (t >> 2) * QREG + (t & 3) * 552;
}

__global__ void __launch_bounds__(512, 1)
attn_kernel(const float* __restrict__ ac,
            const float* __restrict__ alpha,
            const float* __restrict__ wkey,
            const float* __restrict__ u,
            const float* __restrict__ Bv,
            float* __restrict__ Out)
{
    extern __shared__ float sm[];
    unsigned* Pb  = (unsigned*)sm;            // [128][SP] tf32 bits (phys cols)
    unsigned* Xtb = (unsigned*)sm + XT_OFF;   // [64][SP]
    float* invsm = sm + INV_OFF;              // [128]
    float* red = sm + XT_OFF;                 // overlay (after block sync only)

    int bf   = blockIdx.x >> 4;
    int f    = bf & (NF - 1);
    int t0   = (blockIdx.x & 15) << 4;
    int tid  = threadIdx.x;
    int lane = tid & 31;
    int w    = tid >> 5;
    uint32_t smb = smem_u32(sm);

    // ---- cp.async Xt ----
    {
        const unsigned* Xg = g_Xt + (size_t)bf * DIN * NT;
#pragma unroll
        for (int c = 0; c < 8; c++) {
            int i = tid + c * 512;
            int d = i >> 6, l4 = (i & 63) * 4;
            uint32_t dst = smb + (uint32_t)(XT_OFF + d * SP + l4) * 4;
            CP_ASYNC16(dst, Xg + (size_t)d * NT + l4);
        }
        CP_COMMIT();
    }

    int t     = t0 + w;
    int idx_t = bf * NT + t;
    float alpha_f = __ldg(&alpha[f]);
    float a0c = __ldg(&wkey[f*4+0]), b0c = __ldg(&wkey[f*4+1]);
    float a1c = __ldg(&wkey[f*4+2]), b1c = __ldg(&wkey[f*4+3]);
    float v0 = -alpha_f;

    float2 uvj[8];
#pragma unroll
    for (int j = 0; j < 8; j++)
        uvj[j] = __ldg((const float2*)(u + (size_t)f * (NT * 2) + (j * 32 + lane) * 2));
    float rbase = (float)(lane - t);
    int pbase = (lane & ~7) + 2 * (lane & 3) + ((lane >> 2) & 1);

    CP_WAIT0();
    __syncthreads();   // Xt staged

    // ---- scores + softmax (K from L2 g_K2; raw exp stored) ----
#pragma unroll
    for (int hp = 0; hp < 4; hp++) {
        int h0 = hp * 2;
        float4 q4 = __ldg((const float4*)(g_Q + (size_t)idx_t * 16 + h0 * 2));
        float4 k4 = __ldg((const float4*)(g_K + (size_t)idx_t * 16 + h0 * 2));
        float v1a = 2.0f * alpha_f * __ldg(&ac[f * NH + h0]);
        float v1b = 2.0f * alpha_f * __ldg(&ac[f * NH + h0 + 1]);
        float qa0 = q4.x + v0, qa1 = q4.y + v1a;
        float A0 = fmaf(qa0, a0c, qa1 * a1c), B0 = fmaf(qa0, b0c, qa1 * b1c);
        float qb0 = q4.z + v0, qb1 = q4.w + v1b;
        float A1 = fmaf(qb0, a0c, qb1 * a1c), B1 = fmaf(qb0, b0c, qb1 * b1c);

        const float4* Kh = g_K2 + ((size_t)bf * 4 + hp) * NT;
        float s0[8], s1[8], m0 = -3.4e38f, m1 = -3.4e38f;
#pragma unroll
        for (int half = 0; half < 2; half++) {
            float4 kv[4];
#pragma unroll
            for (int j2 = 0; j2 < 4; j2++)
                kv[j2] = __ldg(&Kh[(half * 4 + j2) * 32 + lane]);
#pragma unroll
            for (int j2 = 0; j2 < 4; j2++) {
                int j = half * 4 + j2;
                float r = rbase + 32.0f * j;
                float ut0 = fmaf(uvj[j].x, k4.x, uvj[j].y * k4.y);
                float ut1 = fmaf(uvj[j].x, k4.z, uvj[j].y * k4.w);
                float base0 = fmaf(r, fmaf(A0, r, B0), ut0);
                float base1 = fmaf(r, fmaf(A1, r, B1), ut1);
                base0 = fmaf(q4.x, kv[j2].x, base0); base0 = fmaf(q4.y, kv[j2].y, base0);
                base1 = fmaf(q4.z, kv[j2].z, base1); base1 = fmaf(q4.w, kv[j2].w, base1);
                s0[j] = base0; s1[j] = base1;
                m0 = fmaxf(m0, base0); m1 = fmaxf(m1, base1);
            }
        }
        m0 = warp_max_f32(m0);
        m1 = warp_max_f32(m1);

        unsigned* pr0 = Pb + (8 * w + h0) * SP;
        float sum0 = 0.f, sum1 = 0.f;
#pragma unroll
        for (int j = 0; j < 8; j++) {
            float e0 = __expf(s0[j] - m0);
            float e1 = __expf(s1[j] - m1);
            pr0[j * 32 + pbase]      = f2tf32(e0);
            pr0[SP + j * 32 + pbase] = f2tf32(e1);
            sum0 += e0; sum1 += e1;
        }
#pragma unroll
        for (int o = 16; o; o >>= 1) {
            sum0 += __shfl_xor_sync(0xffffffffu, sum0, o);
            sum1 += __shfl_xor_sync(0xffffffffu, sum1, o);
        }
        if (lane == 0) {
            invsm[8 * w + h0]     = 1.0f / sum0;
            invsm[8 * w + h0 + 1] = 1.0f / sum1;
        }
    }

    // producer: my quad (w>>2) P rows done; consumer: need quad (w&3)
    BAR_ARRIVE(1 + (w >> 2), 256);
    BAR_SYNC(1 + (w & 3), 256);

    // ---- MMA1: warp = (q = w&3 : m32-tile) x (nh : n32-half) x (kh : k128-half)
    int g  = lane >> 2;
    int s4 = lane & 3;
    int q  = w & 3;
    int nh = (w >> 2) & 1;
    int kh = w >> 3;
    int n0 = nh * 32;
    int qb = q * QREG;   // quad region word base

    const uint2* aT0r0 = (const uint2*)(Pb + (32 * q + g) * SP) + s4;
    const uint2* aT0r1 = (const uint2*)(Pb + (32 * q + 8 + g) * SP) + s4;
    const uint2* aT1r0 = (const uint2*)(Pb + (32 * q + 16 + g) * SP) + s4;
    const uint2* aT1r1 = (const uint2*)(Pb + (32 * q + 24 + g) * SP) + s4;
    const uint2* bR0 = (const uint2*)(Xtb + (n0 + 0 + g) * SP) + s4;
    const uint2* bR1 = (const uint2*)(Xtb + (n0 + 8 + g) * SP) + s4;
    const uint2* bR2 = (const uint2*)(Xtb + (n0 + 16 + g) * SP) + s4;
    const uint2* bR3 = (const uint2*)(Xtb + (n0 + 24 + g) * SP) + s4;

    float acc[2][4][4];
#pragma unroll
    for (int i = 0; i < 2; i++)
#pragma unroll
        for (int j = 0; j < 4; j++)
#pragma unroll
            for (int c = 0; c < 4; c++) acc[i][j][c] = 0.f;

    int kio = kh * 64;   // uint2 index offset for this k-half
#pragma unroll 4
    for (int k0 = 0; k0 < 128; k0 += 8) {
        int ki = kio + (k0 >> 1);
        uint2 a0 = aT0r0[ki], a1 = aT0r1[ki];
        uint2 a2 = aT1r0[ki], a3 = aT1r1[ki];
        uint2 b0 = bR0[ki], b1 = bR1[ki], b2 = bR2[ki], b3 = bR3[ki];
        mma8(acc[0][0], a0.x, a1.x, a0.y, a1.y, b0.x, b0.y);
        mma8(acc[0][1], a0.x, a1.x, a0.y, a1.y, b1.x, b1.y);
        mma8(acc[0][2], a0.x, a1.x, a0.y, a1.y, b2.x, b2.y);
        mma8(acc[0][3], a0.x, a1.x, a0.y, a1.y, b3.x, b3.y);
        mma8(acc[1][0], a2.x, a3.x, a2.y, a3.y, b0.x, b0.y);
        mma8(acc[1][1], a2.x, a3.x, a2.y, a3.y, b1.x, b1.y);
        mma8(acc[1][2], a2.x, a3.x, a2.y, a3.y, b2.x, b2.y);
        mma8(acc[1][3], a2.x, a3.x, a2.y, a3.y, b3.x, b3.y);
    }

    // consumers of quad q all done reading its P rows
    BAR_SYNC(5 + q, 128);

    if (kh == 1) {
        // store raw partials into quad scratch: id 0 for w=q+8, 1 for w=q+12
        int id = (w >> 2) - 2;
        float* dst = sm + qb + 2560 + id * 1024 + lane;
#pragma unroll
        for (int i = 0; i < 2; i++)
#pragma unroll
            for (int j = 0; j < 4; j++)
#pragma unroll
                for (int c = 0; c < 4; c++)
                    dst[((i * 4 + j) * 4 + c) * 32] = acc[i][j][c];
    }
    BAR_SYNC(5 + q, 128);

    if (kh == 0) {
        int id = w >> 2;   // 0 pairs with q+8, 1 with q+12 (same nh)
        const float* src = sm + qb + 2560 + id * 1024 + lane;
#pragma unroll
        for (int i = 0; i < 2; i++)
#pragma unroll
            for (int j = 0; j < 4; j++)
#pragma unroll
                for (int c = 0; c < 4; c++)
                    acc[i][j][c] += src[((i * 4 + j) * 4 + c) * 32];

        // normalize + write Av rows t=4q+2mt+rh (h=g), phys cols + h-skew
        int jj = 2 * s4;
        int p0 = 2 * (jj & 3) + ((jj >> 2) & 1);
        int p1 = 2 * ((jj + 1) & 3) + (((jj + 1) >> 2) & 1);
#pragma unroll
        for (int mt = 0; mt < 2; mt++) {
#pragma unroll
            for (int rh = 0; rh < 2; rh++) {
                int tl = 4 * q + 2 * mt + rh;
                float inv = invsm[tl * 8 + g];
                unsigned* av = (unsigned*)sm + av_base(tl) + g * 68;
#pragma unroll
                for (int nt = 0; nt < 4; nt++) {
                    int cb = (n0 + nt * 8) ;   // col group within h
                    av[cb + p0] = f2tf32(acc[mt][nt][2 * rh + 0] * inv);
                    av[cb + p1] = f2tf32(acc[mt][nt][2 * rh + 1] * inv);
                }
            }
        }
    }
    __syncthreads();   // all Av ready; all Xt reads done

    // ---- MMA2: Out[16 t][64 o] = Av @ Wt^T + b.  n-split 8 x k-split 2. ----
    int ni = w & 7;
    int kh2 = w >> 3;
    int n0b = ni * 8;

    float acc2[4] = {0.f, 0.f, 0.f, 0.f};
    const unsigned* avR0 = (unsigned*)sm + av_base(g);
    const unsigned* avR1 = (unsigned*)sm + av_base(g + 8);
    const uint2* wR  = (const uint2*)(g_Wt + (size_t)f * DOUT * NK + (size_t)(n0b + g) * NK) + s4;
#pragma unroll
    for (int kc = kh2 * 4; kc < kh2 * 4 + 4; kc++) {
        int aoff = kc * 68;       // 64 cols + 4 skew per h-group
        int wk = kc * 32;         // uint2 index into Wt row
#pragma unroll
        for (int k8 = 0; k8 < 8; k8++) {
            uint2 a02 = ((const uint2*)(avR0 + aoff + k8 * 8))[s4];
            uint2 a13 = ((const uint2*)(avR1 + aoff + k8 * 8))[s4];
            uint2 b01 = __ldg(&wR[wk + k8 * 4]);
            mma8(acc2, a02.x, a13.x, a02.y, a13.y, b01.x, b01.y);
        }
    }
    __syncthreads();   // Xtb dead -> red
    if (kh2 == 1) {
        float* r = red + (ni * 32 + lane) * 4;
        r[0] = acc2[0]; r[1] = acc2[1]; r[2] = acc2[2]; r[3] = acc2[3];
    }
    __syncthreads();
    if (kh2 == 0) {
        const float* r = red + (ni * 32 + lane) * 4;
        acc2[0] += r[0]; acc2[1] += r[1]; acc2[2] += r[2]; acc2[3] += r[3];

        int tA2 = t0 + g, tB2 = tA2 + 8;
        int oc = n0b + 2 * s4;
        float2 ba = __ldg((const float2*)(Bv + ((size_t)(f * NT + tA2)) * DOUT + oc));
        float2 bb = __ldg((const float2*)(Bv + ((size_t)(f * NT + tB2)) * DOUT + oc));
        *(float2*)(Out + ((size_t)(bf * NT + tA2)) * DOUT + oc) =
            make_float2(acc2[0] + ba.x, acc2[1] + ba.y);
        *(float2*)(Out + ((size_t)(bf * NT + tB2)) * DOUT + oc) =
            make_float2(acc2[2] + bb.x, acc2[3] + bb.y);
    }
}

// ---------------------------------------------------------------------------
extern "C" void kernel_launch(void* const* d_in, const int* in_sizes, int n_in,
                              void* d_out, int out_size)
{
    const float* X     = (const float*)d_in[0];
    const float* ac    = (const float*)d_in[1];
    const float* alpha = (const float*)d_in[2];
    const float* Wq    = (const float*)d_in[3];
    const float* Wk    = (const float*)d_in[4];
    const float* wkey  = (const float*)d_in[5];
    const float* u     = (const float*)d_in[6];
    const float* W     = (const float*)d_in[7];
    const float* Bv    = (const float*)d_in[8];
    float* Out = (float*)d_out;

    cudaFuncSetAttribute(attn_kernel, cudaFuncAttributeMaxDynamicSharedMemorySize, K2_BYTES);

    pre_kernel<<<QK_BLOCKS + XT_BLOCKS + WT_BLOCKS, 256, 64 * 65 * 4>>>(X, Wq, Wk, W);
    attn_kernel<<<BF * 16, 512, K2_BYTES>>>(ac, alpha, wkey, u, Bv, Out);
}

// round 15
// speedup vs baseline: 1.3156x; 1.0101x over previous
#include <cuda_runtime.h>
#include <cstdint>
#include <cstddef>

#define BS 4
#define NF 8
#define NT 256
#define DIN 64
#define NH 8
#define DOUT 64
#define BF (BS*NF)          // 32
#define NK (NH*DIN)         // 512

// Scratch (allocation-free)
__device__ float g_Q[BF * NT * NH * 2];               // [bf][t][h][e]
__device__ float g_K[BF * NT * NH * 2];
__device__ float4 g_K2[BF * 4 * NT];                  // [bf][hp][l]
__device__ unsigned g_Xt[(size_t)BF * DIN * NT];      // tf32 bits, [bf][d][phys(l)]
__device__ unsigned g_Wt[(size_t)NF * DOUT * NK];     // tf32 bits, [f][o][phys(k)]

static __device__ __forceinline__ unsigned f2tf32(float v) {
    unsigned t; asm("cvt.rna.tf32.f32 %0, %1;" : "=r"(t) : "f"(v)); return t;
}
static __device__ __forceinline__ uint32_t smem_u32(const void* p) {
    uint32_t a;
    asm("{ .reg .u64 t; cvta.to.shared.u64 t, %1; cvt.u32.u64 %0, t; }" : "=r"(a) : "l"(p));
    return a;
}
#define CP_ASYNC16(dst, src) \
    asm volatile("cp.async.cg.shared.global [%0], [%1], 16;" :: "r"(dst), "l"(src) : "memory")
#define CP_COMMIT()  asm volatile("cp.async.commit_group;" ::: "memory")
#define CP_WAIT0()   asm volatile("cp.async.wait_group 0;" ::: "memory")
#define BAR_ARRIVE(id, n) asm volatile("bar.arrive %0, %1;" :: "r"(id), "r"(n) : "memory")
#define BAR_SYNC(id, n)   asm volatile("bar.sync %0, %1;"   :: "r"(id), "r"(n) : "memory")

static __device__ __forceinline__ void mma8(float* d, unsigned a0, unsigned a1,
                                            unsigned a2, unsigned a3,
                                            unsigned b0, unsigned b1) {
    asm volatile("mma.sync.aligned.m16n8k8.row.col.f32.tf32.tf32.f32 "
        "{%0,%1,%2,%3}, {%4,%5,%6,%7}, {%8,%9}, {%0,%1,%2,%3};"
        : "+f"(d[0]), "+f"(d[1]), "+f"(d[2]), "+f"(d[3])
        : "r"(a0), "r"(a1), "r"(a2), "r"(a3), "r"(b0), "r"(b1));
}

static __device__ __forceinline__ float warp_max_f32(float x) {
    unsigned b = __float_as_uint(x);
    unsigned e = b ^ (unsigned)(((int)b >> 31) | 0x80000000);
    unsigned r;
    asm volatile("redux.sync.max.u32 %0, %1, 0xffffffff;" : "=r"(r) : "r"(e));
    unsigned bb = ((int)r < 0) ? (r ^ 0x80000000u) : ~r;
    return __uint_as_float(bb);
}

// ---------------------------------------------------------------------------
// Fused pre-kernel (unchanged): [0,1024) QK (+g_K2); X->Xt; W->Wt.
// phys(k) = (k&~7) + 2*(k&3) + ((k>>2)&1)
// ---------------------------------------------------------------------------
#define QK_BLOCKS 1024
#define XT_BLOCKS 128
#define WT_BLOCKS 64

__global__ void __launch_bounds__(256)
pre_kernel(const float* __restrict__ X,
           const float* __restrict__ Wq,
           const float* __restrict__ Wk,
           const float* __restrict__ W)
{
    extern __shared__ float tsm[];   // [64][65]
    int tid = threadIdx.x;

    if (blockIdx.x < QK_BLOCKS) {
        int idx  = blockIdx.x * 8 + (tid >> 5);
        int lane = tid & 31;
        int t_ft = idx & (NF * NT - 1);

        const float* x = X + (size_t)idx * DIN;
        float x0 = __ldg(&x[lane]);
        float x1 = __ldg(&x[lane + 32]);

        int dq = lane >> 2;
        const float4* Wq4 = (const float4*)(Wq + (size_t)t_ft * (DIN * 16));
        const float4* Wk4 = (const float4*)(Wk + (size_t)t_ft * (DIN * 16));

        float4 wq[8], wk[8];
#pragma unroll
        for (int i = 0; i < 8; i++) {
            wq[i] = __ldg(&Wq4[i * 32 + lane]);
            wk[i] = __ldg(&Wk4[i * 32 + lane]);
        }
        float4 aq = {0,0,0,0}, ak = {0,0,0,0};
#pragma unroll
        for (int i = 0; i < 8; i++) {
            int dsel = (i & 3) * 8 + dq;
            float xv = __shfl_sync(0xffffffffu, (i < 4) ? x0 : x1, dsel);
            aq.x = fmaf(xv, wq[i].x, aq.x); aq.y = fmaf(xv, wq[i].y, aq.y);
            aq.z = fmaf(xv, wq[i].z, aq.z); aq.w = fmaf(xv, wq[i].w, aq.w);
            ak.x = fmaf(xv, wk[i].x, ak.x); ak.y = fmaf(xv, wk[i].y, ak.y);
            ak.z = fmaf(xv, wk[i].z, ak.z); ak.w = fmaf(xv, wk[i].w, ak.w);
        }
#pragma unroll
        for (int off = 16; off >= 4; off >>= 1) {
            aq.x += __shfl_xor_sync(0xffffffffu, aq.x, off);
            aq.y += __shfl_xor_sync(0xffffffffu, aq.y, off);
            aq.z += __shfl_xor_sync(0xffffffffu, aq.z, off);
            aq.w += __shfl_xor_sync(0xffffffffu, aq.w, off);
            ak.x += __shfl_xor_sync(0xffffffffu, ak.x, off);
            ak.y += __shfl_xor_sync(0xffffffffu, ak.y, off);
            ak.z += __shfl_xor_sync(0xffffffffu, ak.z, off);
            ak.w += __shfl_xor_sync(0xffffffffu, ak.w, off);
        }
        if (lane < 4) {
            *(float4*)(g_Q + (size_t)idx * 16 + lane * 4) = aq;
        } else if (lane < 8) {
            *(float4*)(g_K + (size_t)idx * 16 + (lane - 4) * 4) = ak;
            int hp = lane - 4;
            g_K2[((size_t)(idx >> 8) * 4 + hp) * NT + (idx & 255)] = ak;
        }
    }
    else if (blockIdx.x < QK_BLOCKS + XT_BLOCKS) {
        int b  = blockIdx.x - QK_BLOCKS;
        int bf = b >> 2, lc = b & 3;
        const float4* src = (const float4*)(X + ((size_t)bf * NT + lc * 64) * DIN);
        for (int i = tid; i < 64 * 16; i += 256) {
            int r = i >> 4, c0 = (i & 15) * 4;
            float4 v = __ldg(&src[i]);
            tsm[r * 65 + c0 + 0] = v.x;
            tsm[r * 65 + c0 + 1] = v.y;
            tsm[r * 65 + c0 + 2] = v.z;
            tsm[r * 65 + c0 + 3] = v.w;
        }
        __syncthreads();
        unsigned* dst = g_Xt + (size_t)bf * (DIN * NT) + lc * 64;
        for (int i = tid; i < 64 * 32; i += 256) {
            int d = i >> 5, p = i & 31;
            int g8 = p >> 2, s = p & 3;
            int la = g8 * 8 + s, lb = la + 4;
            uint2 o;
            o.x = f2tf32(tsm[la * 65 + d]);
            o.y = f2tf32(tsm[lb * 65 + d]);
            *(uint2*)(dst + (size_t)d * NT + g8 * 8 + 2 * s) = o;
        }
    }
    else {
        int b  = blockIdx.x - QK_BLOCKS - XT_BLOCKS;
        int f = b >> 3, kc = b & 7;
        const float4* src = (const float4*)(W + ((size_t)f * NK + kc * 64) * DOUT);
        for (int i = tid; i < 64 * 16; i += 256) {
            int r = i >> 4, c0 = (i & 15) * 4;
            float4 v = __ldg(&src[i]);
            tsm[r * 65 + c0 + 0] = v.x;
            tsm[r * 65 + c0 + 1] = v.y;
            tsm[r * 65 + c0 + 2] = v.z;
            tsm[r * 65 + c0 + 3] = v.w;
        }
        __syncthreads();
        unsigned* dst = g_Wt + (size_t)f * (DOUT * NK) + kc * 64;
        for (int i = tid; i < 64 * 32; i += 256) {
            int o = i >> 5, p = i & 31;
            int g8 = p >> 2, s = p & 3;
            int ka = g8 * 8 + s, kb = ka + 4;
            uint2 ov;
            ov.x = f2tf32(tsm[ka * 65 + o]);
            ov.y = f2tf32(tsm[kb * 65 + o]);
            *(uint2*)(dst + (size_t)o * NK + g8 * 8 + 2 * s) = ov;
        }
    }
}

// ---------------------------------------------------------------------------
// FUSED attn, m32n32k2 MMA1 retile + quad arrive/sync decoupling.
// Round-15: Xt wait deferred past softmax hp=0; kv/uv full-depth batching.
// grid = BF*16 = 512, 512 threads.
// smem words: P[128][264] | Xt[64][264] | invsm[128]  -> 203264 B
// ---------------------------------------------------------------------------
#define SP 264
#define QREG (32*SP)                 // 8448 words per quad region
#define XT_OFF (128*SP)              // 33792
#define INV_OFF (XT_OFF + 64*SP)     // 50688
#define K2_BYTES ((INV_OFF + 128)*4) // 203264

static __device__ __forceinline__ int av_base(int t) {
    return (t >> 2) * QREG + (t & 3) * 552;
}

__global__ void __launch_bounds__(512, 1)
attn_kernel(const float* __restrict__ ac,
            const float* __restrict__ alpha,
            const float* __restrict__ wkey,
            const float* __restrict__ u,
            const float* __restrict__ Bv,
            float* __restrict__ Out)
{
    extern __shared__ float sm[];
    unsigned* Pb  = (unsigned*)sm;            // [128][SP] tf32 bits (phys cols)
    unsigned* Xtb = (unsigned*)sm + XT_OFF;   // [64][SP]
    float* invsm = sm + INV_OFF;              // [128]
    float* red = sm + XT_OFF;                 // overlay (after block sync only)

    int bf   = blockIdx.x >> 4;
    int f    = bf & (NF - 1);
    int t0   = (blockIdx.x & 15) << 4;
    int tid  = threadIdx.x;
    int lane = tid & 31;
    int w    = tid >> 5;
    uint32_t smb = smem_u32(sm);

    // ---- cp.async Xt (lands during softmax hp=0) ----
    {
        const unsigned* Xg = g_Xt + (size_t)bf * DIN * NT;
#pragma unroll
        for (int c = 0; c < 8; c++) {
            int i = tid + c * 512;
            int d = i >> 6, l4 = (i & 63) * 4;
            uint32_t dst = smb + (uint32_t)(XT_OFF + d * SP + l4) * 4;
            CP_ASYNC16(dst, Xg + (size_t)d * NT + l4);
        }
        CP_COMMIT();
    }

    int t     = t0 + w;
    int idx_t = bf * NT + t;
    float alpha_f = __ldg(&alpha[f]);
    float a0c = __ldg(&wkey[f*4+0]), b0c = __ldg(&wkey[f*4+1]);
    float a1c = __ldg(&wkey[f*4+2]), b1c = __ldg(&wkey[f*4+3]);
    float v0 = -alpha_f;
    float rbase = (float)(lane - t);
    int pbase = (lane & ~7) + 2 * (lane & 3) + ((lane >> 2) & 1);
    const float* uf = u + (size_t)f * (NT * 2);

    // ---- scores + softmax (K,u fully batched from L2; raw exp stored) ----
#pragma unroll
    for (int hp = 0; hp < 4; hp++) {
        int h0 = hp * 2;
        float4 q4 = __ldg((const float4*)(g_Q + (size_t)idx_t * 16 + h0 * 2));
        float4 k4 = __ldg((const float4*)(g_K + (size_t)idx_t * 16 + h0 * 2));
        float v1a = 2.0f * alpha_f * __ldg(&ac[f * NH + h0]);
        float v1b = 2.0f * alpha_f * __ldg(&ac[f * NH + h0 + 1]);
        float qa0 = q4.x + v0, qa1 = q4.y + v1a;
        float A0 = fmaf(qa0, a0c, qa1 * a1c), B0 = fmaf(qa0, b0c, qa1 * b1c);
        float qb0 = q4.z + v0, qb1 = q4.w + v1b;
        float A1 = fmaf(qb0, a0c, qb1 * a1c), B1 = fmaf(qb0, b0c, qb1 * b1c);

        const float4* Kh = g_K2 + ((size_t)bf * 4 + hp) * NT;
        float4 kv[8];
        float2 uv[8];
#pragma unroll
        for (int j = 0; j < 8; j++) {
            kv[j] = __ldg(&Kh[j * 32 + lane]);
            uv[j] = __ldg((const float2*)(uf + (j * 32 + lane) * 2));
        }

        float s0[8], s1[8], m0 = -3.4e38f, m1 = -3.4e38f;
#pragma unroll
        for (int j = 0; j < 8; j++) {
            float r = rbase + 32.0f * j;
            float ut0 = fmaf(uv[j].x, k4.x, uv[j].y * k4.y);
            float ut1 = fmaf(uv[j].x, k4.z, uv[j].y * k4.w);
            float base0 = fmaf(r, fmaf(A0, r, B0), ut0);
            float base1 = fmaf(r, fmaf(A1, r, B1), ut1);
            base0 = fmaf(q4.x, kv[j].x, base0); base0 = fmaf(q4.y, kv[j].y, base0);
            base1 = fmaf(q4.z, kv[j].z, base1); base1 = fmaf(q4.w, kv[j].w, base1);
            s0[j] = base0; s1[j] = base1;
            m0 = fmaxf(m0, base0); m1 = fmaxf(m1, base1);
        }
        m0 = warp_max_f32(m0);
        m1 = warp_max_f32(m1);

        unsigned* pr0 = Pb + (8 * w + h0) * SP;
        float sum0 = 0.f, sum1 = 0.f;
#pragma unroll
        for (int j = 0; j < 8; j++) {
            float e0 = __expf(s0[j] - m0);
            float e1 = __expf(s1[j] - m1);
            pr0[j * 32 + pbase]      = f2tf32(e0);
            pr0[SP + j * 32 + pbase] = f2tf32(e1);
            sum0 += e0; sum1 += e1;
        }
#pragma unroll
        for (int o = 16; o; o >>= 1) {
            sum0 += __shfl_xor_sync(0xffffffffu, sum0, o);
            sum1 += __shfl_xor_sync(0xffffffffu, sum1, o);
        }
        if (lane == 0) {
            invsm[8 * w + h0]     = 1.0f / sum0;
            invsm[8 * w + h0 + 1] = 1.0f / sum1;
        }
        if (hp == 0) {           // Xt copies have had ~1/4 of softmax to land
            CP_WAIT0();
            __syncthreads();
        }
    }

    // producer: my quad (w>>2) P rows done; consumer: need quad (w&3)
    BAR_ARRIVE(1 + (w >> 2), 256);
    BAR_SYNC(1 + (w & 3), 256);

    // ---- MMA1: warp = (q = w&3 : m32-tile) x (nh : n32-half) x (kh : k128-half)
    int g  = lane >> 2;
    int s4 = lane & 3;
    int q  = w & 3;
    int nh = (w >> 2) & 1;
    int kh = w >> 3;
    int n0 = nh * 32;
    int qb = q * QREG;

    const uint2* aT0r0 = (const uint2*)(Pb + (32 * q + g) * SP) + s4;
    const uint2* aT0r1 = (const uint2*)(Pb + (32 * q + 8 + g) * SP) + s4;
    const uint2* aT1r0 = (const uint2*)(Pb + (32 * q + 16 + g) * SP) + s4;
    const uint2* aT1r1 = (const uint2*)(Pb + (32 * q + 24 + g) * SP) + s4;
    const uint2* bR0 = (const uint2*)(Xtb + (n0 + 0 + g) * SP) + s4;
    const uint2* bR1 = (const uint2*)(Xtb + (n0 + 8 + g) * SP) + s4;
    const uint2* bR2 = (const uint2*)(Xtb + (n0 + 16 + g) * SP) + s4;
    const uint2* bR3 = (const uint2*)(Xtb + (n0 + 24 + g) * SP) + s4;

    float acc[2][4][4];
#pragma unroll
    for (int i = 0; i < 2; i++)
#pragma unroll
        for (int j = 0; j < 4; j++)
#pragma unroll
            for (int c = 0; c < 4; c++) acc[i][j][c] = 0.f;

    int kio = kh * 64;
#pragma unroll 4
    for (int k0 = 0; k0 < 128; k0 += 8) {
        int ki = kio + (k0 >> 1);
        uint2 a0 = aT0r0[ki], a1 = aT0r1[ki];
        uint2 a2 = aT1r0[ki], a3 = aT1r1[ki];
        uint2 b0 = bR0[ki], b1 = bR1[ki], b2 = bR2[ki], b3 = bR3[ki];
        mma8(acc[0][0], a0.x, a1.x, a0.y, a1.y, b0.x, b0.y);
        mma8(acc[0][1], a0.x, a1.x, a0.y, a1.y, b1.x, b1.y);
        mma8(acc[0][2], a0.x, a1.x, a0.y, a1.y, b2.x, b2.y);
        mma8(acc[0][3], a0.x, a1.x, a0.y, a1.y, b3.x, b3.y);
        mma8(acc[1][0], a2.x, a3.x, a2.y, a3.y, b0.x, b0.y);
        mma8(acc[1][1], a2.x, a3.x, a2.y, a3.y, b1.x, b1.y);
        mma8(acc[1][2], a2.x, a3.x, a2.y, a3.y, b2.x, b2.y);
        mma8(acc[1][3], a2.x, a3.x, a2.y, a3.y, b3.x, b3.y);
    }

    BAR_SYNC(5 + q, 128);

    if (kh == 1) {
        int id = (w >> 2) - 2;
        float* dst = sm + qb + 2560 + id * 1024 + lane;
#pragma unroll
        for (int i = 0; i < 2; i++)
#pragma unroll
            for (int j = 0; j < 4; j++)
#pragma unroll
                for (int c = 0; c < 4; c++)
                    dst[((i * 4 + j) * 4 + c) * 32] = acc[i][j][c];
    }
    BAR_SYNC(5 + q, 128);

    if (kh == 0) {
        int id = w >> 2;
        const float* src = sm + qb + 2560 + id * 1024 + lane;
#pragma unroll
        for (int i = 0; i < 2; i++)
#pragma unroll
            for (int j = 0; j < 4; j++)
#pragma unroll
                for (int c = 0; c < 4; c++)
                    acc[i][j][c] += src[((i * 4 + j) * 4 + c) * 32];

        int jj = 2 * s4;
        int p0 = 2 * (jj & 3) + ((jj >> 2) & 1);
        int p1 = 2 * ((jj + 1) & 3) + (((jj + 1) >> 2) & 1);
#pragma unroll
        for (int mt = 0; mt < 2; mt++) {
#pragma unroll
            for (int rh = 0; rh < 2; rh++) {
                int tl = 4 * q + 2 * mt + rh;
                float inv = invsm[tl * 8 + g];
                unsigned* av = (unsigned*)sm + av_base(tl) + g * 68;
#pragma unroll
                for (int nt = 0; nt < 4; nt++) {
                    int cb = n0 + nt * 8;
                    av[cb + p0] = f2tf32(acc[mt][nt][2 * rh + 0] * inv);
                    av[cb + p1] = f2tf32(acc[mt][nt][2 * rh + 1] * inv);
                }
            }
        }
    }
    __syncthreads();   // all Av ready; all Xt reads done

    // ---- MMA2: Out[16 t][64 o] = Av @ Wt^T + b.  n-split 8 x k-split 2. ----
    int ni = w & 7;
    int kh2 = w >> 3;
    int n0b = ni * 8;

    float acc2[4] = {0.f, 0.f, 0.f, 0.f};
    const unsigned* avR0 = (unsigned*)sm + av_base(g);
    const unsigned* avR1 = (unsigned*)sm + av_base(g + 8);
    const uint2* wR  = (const uint2*)(g_Wt + (size_t)f * DOUT * NK + (size_t)(n0b + g) * NK) + s4;
#pragma unroll
    for (int kc = kh2 * 4; kc < kh2 * 4 + 4; kc++) {
        int aoff = kc * 68;
        int wk = kc * 32;
#pragma unroll
        for (int k8 = 0; k8 < 8; k8++) {
            uint2 a02 = ((const uint2*)(avR0 + aoff + k8 * 8))[s4];
            uint2 a13 = ((const uint2*)(avR1 + aoff + k8 * 8))[s4];
            uint2 b01 = __ldg(&wR[wk + k8 * 4]);
            mma8(acc2, a02.x, a13.x, a02.y, a13.y, b01.x, b01.y);
        }
    }
    __syncthreads();   // Xtb dead -> red
    if (kh2 == 1) {
        float* r = red + (ni * 32 + lane) * 4;
        r[0] = acc2[0]; r[1] = acc2[1]; r[2] = acc2[2]; r[3] = acc2[3];
    }
    __syncthreads();
    if (kh2 == 0) {
        const float* r = red + (ni * 32 + lane) * 4;
        acc2[0] += r[0]; acc2[1] += r[1]; acc2[2] += r[2]; acc2[3] += r[3];

        int tA2 = t0 + g, tB2 = tA2 + 8;
        int oc = n0b + 2 * s4;
        float2 ba = __ldg((const float2*)(Bv + ((size_t)(f * NT + tA2)) * DOUT + oc));
        float2 bb = __ldg((const float2*)(Bv + ((size_t)(f * NT + tB2)) * DOUT + oc));
        *(float2*)(Out + ((size_t)(bf * NT + tA2)) * DOUT + oc) =
            make_float2(acc2[0] + ba.x, acc2[1] + ba.y);
        *(float2*)(Out + ((size_t)(bf * NT + tB2)) * DOUT + oc) =
            make_float2(acc2[2] + bb.x, acc2[3] + bb.y);
    }
}

// ---------------------------------------------------------------------------
extern "C" void kernel_launch(void* const* d_in, const int* in_sizes, int n_in,
                              void* d_out, int out_size)
{
    const float* X     = (const float*)d_in[0];
    const float* ac    = (const float*)d_in[1];
    const float* alpha = (const float*)d_in[2];
    const float* Wq    = (const float*)d_in[3];
    const float* Wk    = (const float*)d_in[4];
    const float* wkey  = (const float*)d_in[5];
    const float* u     = (const float*)d_in[6];
    const float* W     = (const float*)d_in[7];
    const float* Bv    = (const float*)d_in[8];
    float* Out = (float*)d_out;

    cudaFuncSetAttribute(attn_kernel, cudaFuncAttributeMaxDynamicSharedMemorySize, K2_BYTES);

    pre_kernel<<<QK_BLOCKS + XT_BLOCKS + WT_BLOCKS, 256, 64 * 65 * 4>>>(X, Wq, Wk, W);
    attn_kernel<<<BF * 16, 512, K2_BYTES>>>(ac, alpha, wkey, u, Bv, Out);
}

// round 16
// speedup vs baseline: 1.5560x; 1.1827x over previous
#include <cuda_runtime.h>
#include <cuda_fp16.h>
#include <cstdint>
#include <cstddef>

#define BS 4
#define NF 8
#define NT 256
#define DIN 64
#define NH 8
#define DOUT 64
#define BF (BS*NF)          // 32
#define NK (NH*DIN)         // 512

// Scratch (allocation-free)
__device__ float g_Q[BF * NT * NH * 2];               // [bf][t][h][e]
__device__ float g_K[BF * NT * NH * 2];
__device__ float4 g_K2[BF * 4 * NT];                  // [bf][hp][l]
__device__ __half g_Xt16[(size_t)BF * DIN * NT];      // [bf][d][phys16(l)]
__device__ __half g_Wt16[(size_t)NF * DOUT * NK];     // [f][o][phys16(k)]

static __device__ __forceinline__ uint32_t smem_u32(const void* p) {
    uint32_t a;
    asm("{ .reg .u64 t; cvta.to.shared.u64 t, %1; cvt.u32.u64 %0, t; }" : "=r"(a) : "l"(p));
    return a;
}
#define CP_ASYNC16(dst, src) \
    asm volatile("cp.async.cg.shared.global [%0], [%1], 16;" :: "r"(dst), "l"(src) : "memory")
#define CP_COMMIT()  asm volatile("cp.async.commit_group;" ::: "memory")
#define CP_WAIT0()   asm volatile("cp.async.wait_group 0;" ::: "memory")
#define BAR_ARRIVE(id, n) asm volatile("bar.arrive %0, %1;" :: "r"(id), "r"(n) : "memory")
#define BAR_SYNC(id, n)   asm volatile("bar.sync %0, %1;"   :: "r"(id), "r"(n) : "memory")

// m16n8k16 fp16 MMA, fp32 accum
static __device__ __forceinline__ void mma16(float* d, unsigned a0, unsigned a1,
                                             unsigned a2, unsigned a3,
                                             unsigned b0, unsigned b1) {
    asm volatile("mma.sync.aligned.m16n8k16.row.col.f32.f16.f16.f32 "
        "{%0,%1,%2,%3}, {%4,%5,%6,%7}, {%8,%9}, {%0,%1,%2,%3};"
        : "+f"(d[0]), "+f"(d[1]), "+f"(d[2]), "+f"(d[3])
        : "r"(a0), "r"(a1), "r"(a2), "r"(a3), "r"(b0), "r"(b1));
}

static __device__ __forceinline__ float warp_max_f32(float x) {
    unsigned b = __float_as_uint(x);
    unsigned e = b ^ (unsigned)(((int)b >> 31) | 0x80000000);
    unsigned r;
    asm volatile("redux.sync.max.u32 %0, %1, 0xffffffff;" : "=r"(r) : "r"(e));
    unsigned bb = ((int)r < 0) ? (r ^ 0x80000000u) : ~r;
    return __uint_as_float(bb);
}

// phys16 slot of halfword k within its 16-block: pairs (2m,2m+1) -> slots
// [0,1,8,9, 2,3,10,11, 4,5,12,13, 6,7,14,15]
static __device__ __forceinline__ int slot16(int m) {   // m = (k>>1)&7
    return 4 * (m & 3) + 2 * (m >> 2);
}

// ---------------------------------------------------------------------------
// pre-kernel: [0,1024) QK (+g_K2); [1024,1152) X->Xt16; [1152,1216) W->Wt16.
// ---------------------------------------------------------------------------
#define QK_BLOCKS 1024
#define XT_BLOCKS 128
#define WT_BLOCKS 64

__global__ void __launch_bounds__(256)
pre_kernel(const float* __restrict__ X,
           const float* __restrict__ Wq,
           const float* __restrict__ Wk,
           const float* __restrict__ W)
{
    extern __shared__ float tsm[];   // [64][65]
    int tid = threadIdx.x;

    if (blockIdx.x < QK_BLOCKS) {
        int idx  = blockIdx.x * 8 + (tid >> 5);
        int lane = tid & 31;
        int t_ft = idx & (NF * NT - 1);

        const float* x = X + (size_t)idx * DIN;
        float x0 = __ldg(&x[lane]);
        float x1 = __ldg(&x[lane + 32]);

        int dq = lane >> 2;
        const float4* Wq4 = (const float4*)(Wq + (size_t)t_ft * (DIN * 16));
        const float4* Wk4 = (const float4*)(Wk + (size_t)t_ft * (DIN * 16));

        float4 wq[8], wk[8];
#pragma unroll
        for (int i = 0; i < 8; i++) {
            wq[i] = __ldg(&Wq4[i * 32 + lane]);
            wk[i] = __ldg(&Wk4[i * 32 + lane]);
        }
        float4 aq = {0,0,0,0}, ak = {0,0,0,0};
#pragma unroll
        for (int i = 0; i < 8; i++) {
            int dsel = (i & 3) * 8 + dq;
            float xv = __shfl_sync(0xffffffffu, (i < 4) ? x0 : x1, dsel);
            aq.x = fmaf(xv, wq[i].x, aq.x); aq.y = fmaf(xv, wq[i].y, aq.y);
            aq.z = fmaf(xv, wq[i].z, aq.z); aq.w = fmaf(xv, wq[i].w, aq.w);
            ak.x = fmaf(xv, wk[i].x, ak.x); ak.y = fmaf(xv, wk[i].y, ak.y);
            ak.z = fmaf(xv, wk[i].z, ak.z); ak.w = fmaf(xv, wk[i].w, ak.w);
        }
#pragma unroll
        for (int off = 16; off >= 4; off >>= 1) {
            aq.x += __shfl_xor_sync(0xffffffffu, aq.x, off);
            aq.y += __shfl_xor_sync(0xffffffffu, aq.y, off);
            aq.z += __shfl_xor_sync(0xffffffffu, aq.z, off);
            aq.w += __shfl_xor_sync(0xffffffffu, aq.w, off);
            ak.x += __shfl_xor_sync(0xffffffffu, ak.x, off);
            ak.y += __shfl_xor_sync(0xffffffffu, ak.y, off);
            ak.z += __shfl_xor_sync(0xffffffffu, ak.z, off);
            ak.w += __shfl_xor_sync(0xffffffffu, ak.w, off);
        }
        if (lane < 4) {
            *(float4*)(g_Q + (size_t)idx * 16 + lane * 4) = aq;
        } else if (lane < 8) {
            *(float4*)(g_K + (size_t)idx * 16 + (lane - 4) * 4) = ak;
            int hp = lane - 4;
            g_K2[((size_t)(idx >> 8) * 4 + hp) * NT + (idx & 255)] = ak;
        }
    }
    else if (blockIdx.x < QK_BLOCKS + XT_BLOCKS) {
        // X[bf][lc*64+r][d] -> g_Xt16[bf][d][lc*64 + phys16(r)]
        int b  = blockIdx.x - QK_BLOCKS;
        int bf = b >> 2, lc = b & 3;
        const float4* src = (const float4*)(X + ((size_t)bf * NT + lc * 64) * DIN);
        for (int i = tid; i < 64 * 16; i += 256) {
            int r = i >> 4, c0 = (i & 15) * 4;
            float4 v = __ldg(&src[i]);
            tsm[r * 65 + c0 + 0] = v.x;
            tsm[r * 65 + c0 + 1] = v.y;
            tsm[r * 65 + c0 + 2] = v.z;
            tsm[r * 65 + c0 + 3] = v.w;
        }
        __syncthreads();
        __half* dst = g_Xt16 + (size_t)bf * (DIN * NT) + lc * 64;
        for (int i = tid; i < 64 * 32; i += 256) {
            int d = i >> 5, p = i & 31;
            int la = 2 * p, lb = la + 1;
            int blk = p >> 3, m = p & 7;
            __half2 v = __floats2half2_rn(tsm[la * 65 + d], tsm[lb * 65 + d]);
            *(__half2*)(dst + (size_t)d * NT + blk * 16 + slot16(m)) = v;
        }
    }
    else {
        // W[f][kc*64+r][o] -> g_Wt16[f][o][kc*64 + phys16(r)]
        int b  = blockIdx.x - QK_BLOCKS - XT_BLOCKS;
        int f = b >> 3, kc = b & 7;
        const float4* src = (const float4*)(W + ((size_t)f * NK + kc * 64) * DOUT);
        for (int i = tid; i < 64 * 16; i += 256) {
            int r = i >> 4, c0 = (i & 15) * 4;
            float4 v = __ldg(&src[i]);
            tsm[r * 65 + c0 + 0] = v.x;
            tsm[r * 65 + c0 + 1] = v.y;
            tsm[r * 65 + c0 + 2] = v.z;
            tsm[r * 65 + c0 + 3] = v.w;
        }
        __syncthreads();
        __half* dst = g_Wt16 + (size_t)f * (DOUT * NK) + kc * 64;
        for (int i = tid; i < 64 * 32; i += 256) {
            int o = i >> 5, p = i & 31;
            int ka = 2 * p, kb = ka + 1;
            int blk = p >> 3, m = p & 7;
            __half2 v = __floats2half2_rn(tsm[ka * 65 + o], tsm[kb * 65 + o]);
            *(__half2*)(dst + (size_t)o * NK + blk * 16 + slot16(m)) = v;
        }
    }
}

// ---------------------------------------------------------------------------
// FUSED attn (fp16 MMA path).  grid = BF*16, 512 threads.
// smem (halfwords unless noted):
//   P   [128][272]   @H 0        (69632 B)
//   Xt  [64][272]    @H 34816    (34816 B)
//   Av  16 rows, row t @ H 52224 + t*640 + 16*(t&3), h-chunk stride 68
//   invsm [128] floats @ byte 124928;  total 125440 B
// Exchange scratch overlays quad's P region; red overlays Xt.
// ---------------------------------------------------------------------------
#define SPH 272
#define XT_H 34816
#define AV_H 52224
#define SMEM_BYTES 125440

__global__ void __launch_bounds__(512, 1)
attn_kernel(const float* __restrict__ ac,
            const float* __restrict__ alpha,
            const float* __restrict__ wkey,
            const float* __restrict__ u,
            const float* __restrict__ Bv,
            float* __restrict__ Out)
{
    extern __shared__ float sm[];
    char* smc = (char*)sm;
    __half* smh = (__half*)sm;
    float* invsm = (float*)(smc + 124928);
    float* red = (float*)(smc + 69632);     // overlays Xt (post MMA2 compute)

    int bf   = blockIdx.x >> 4;
    int f    = bf & (NF - 1);
    int t0   = (blockIdx.x & 15) << 4;
    int tid  = threadIdx.x;
    int lane = tid & 31;
    int w    = tid >> 5;
    uint32_t smb = smem_u32(sm);

    // ---- cp.async Xt16 (lands during softmax hp=0) ----
    {
        const __half* Xg = g_Xt16 + (size_t)bf * DIN * NT;
#pragma unroll
        for (int c = 0; c < 4; c++) {
            int i = tid + c * 512;               // 2048 chunks of 16B
            int d = i >> 5, ch = i & 31;
            uint32_t dst = smb + (uint32_t)(69632 + d * 544 + ch * 16);
            CP_ASYNC16(dst, Xg + (size_t)d * NT + ch * 8);
        }
        CP_COMMIT();
    }

    int t     = t0 + w;
    int idx_t = bf * NT + t;
    float alpha_f = __ldg(&alpha[f]);
    float a0c = __ldg(&wkey[f*4+0]), b0c = __ldg(&wkey[f*4+1]);
    float a1c = __ldg(&wkey[f*4+2]), b1c = __ldg(&wkey[f*4+3]);
    float v0 = -alpha_f;
    float rbase = (float)(lane - t);
    const float* uf = u + (size_t)f * (NT * 2);

    // ---- scores + softmax (fp32; raw exp stored as fp16 pairs) ----
#pragma unroll
    for (int hp = 0; hp < 4; hp++) {
        int h0 = hp * 2;
        float4 q4 = __ldg((const float4*)(g_Q + (size_t)idx_t * 16 + h0 * 2));
        float4 k4 = __ldg((const float4*)(g_K + (size_t)idx_t * 16 + h0 * 2));
        float v1a = 2.0f * alpha_f * __ldg(&ac[f * NH + h0]);
        float v1b = 2.0f * alpha_f * __ldg(&ac[f * NH + h0 + 1]);
        float qa0 = q4.x + v0, qa1 = q4.y + v1a;
        float A0 = fmaf(qa0, a0c, qa1 * a1c), B0 = fmaf(qa0, b0c, qa1 * b1c);
        float qb0 = q4.z + v0, qb1 = q4.w + v1b;
        float A1 = fmaf(qb0, a0c, qb1 * a1c), B1 = fmaf(qb0, b0c, qb1 * b1c);

        const float4* Kh = g_K2 + ((size_t)bf * 4 + hp) * NT;
        float4 kv[8];
        float2 uv[8];
#pragma unroll
        for (int j = 0; j < 8; j++) {
            kv[j] = __ldg(&Kh[j * 32 + lane]);
            uv[j] = __ldg((const float2*)(uf + (j * 32 + lane) * 2));
        }

        float s0[8], s1[8], m0 = -3.4e38f, m1 = -3.4e38f;
#pragma unroll
        for (int j = 0; j < 8; j++) {
            float r = rbase + 32.0f * j;
            float ut0 = fmaf(uv[j].x, k4.x, uv[j].y * k4.y);
            float ut1 = fmaf(uv[j].x, k4.z, uv[j].y * k4.w);
            float base0 = fmaf(r, fmaf(A0, r, B0), ut0);
            float base1 = fmaf(r, fmaf(A1, r, B1), ut1);
            base0 = fmaf(q4.x, kv[j].x, base0); base0 = fmaf(q4.y, kv[j].y, base0);
            base1 = fmaf(q4.z, kv[j].z, base1); base1 = fmaf(q4.w, kv[j].w, base1);
            s0[j] = base0; s1[j] = base1;
            m0 = fmaxf(m0, base0); m1 = fmaxf(m1, base1);
        }
        m0 = warp_max_f32(m0);
        m1 = warp_max_f32(m1);

        int rowH0 = (8 * w + h0) * SPH;
        float sum0 = 0.f, sum1 = 0.f;
#pragma unroll
        for (int j = 0; j < 8; j++) {
            float e0 = __expf(s0[j] - m0);
            float e1 = __expf(s1[j] - m1);
            sum0 += e0; sum1 += e1;
            float e0n = __shfl_down_sync(0xffffffffu, e0, 1);
            float e1n = __shfl_down_sync(0xffffffffu, e1, 1);
            if (!(lane & 1)) {
                int l = j * 32 + lane;
                int m = (l >> 1) & 7;
                int pos = ((l >> 4) << 4) + slot16(m);
                *(__half2*)(smh + rowH0 + pos)       = __floats2half2_rn(e0, e0n);
                *(__half2*)(smh + rowH0 + SPH + pos) = __floats2half2_rn(e1, e1n);
            }
        }
#pragma unroll
        for (int o = 16; o; o >>= 1) {
            sum0 += __shfl_xor_sync(0xffffffffu, sum0, o);
            sum1 += __shfl_xor_sync(0xffffffffu, sum1, o);
        }
        if (lane == 0) {
            invsm[8 * w + h0]     = 1.0f / sum0;
            invsm[8 * w + h0 + 1] = 1.0f / sum1;
        }
        if (hp == 0) {
            CP_WAIT0();
            __syncthreads();
        }
    }

    BAR_ARRIVE(1 + (w >> 2), 256);
    BAR_SYNC(1 + (w & 3), 256);

    // ---- MMA1: warp = (q m32) x (nh n32) x (kh k128).  LDS.64 fragments. ----
    int g  = lane >> 2;
    int s4 = lane & 3;
    int q  = w & 3;
    int nh = (w >> 2) & 1;
    int kh = w >> 3;
    int n0 = nh * 32;

    const uint2* smu = (const uint2*)sm;   // idx = halfword/4
    int ko0 = kh * 32;                     // kh*128 halfwords /4
    int rA0 = (32 * q + g) * 68 + s4 + ko0;
    int rA1 = rA0 + 8 * 68;
    int rA2 = rA0 + 16 * 68;
    int rA3 = rA0 + 24 * 68;
    int rB0 = 8704 + (n0 + g) * 68 + s4 + ko0;
    int rB1 = rB0 + 8 * 68;
    int rB2 = rB0 + 16 * 68;
    int rB3 = rB0 + 24 * 68;

    float acc[2][4][4];
#pragma unroll
    for (int i = 0; i < 2; i++)
#pragma unroll
        for (int j = 0; j < 4; j++)
#pragma unroll
            for (int c = 0; c < 4; c++) acc[i][j][c] = 0.f;

#pragma unroll
    for (int st = 0; st < 8; st++) {
        int ko = st * 4;
        uint2 A0 = smu[rA0 + ko], A1 = smu[rA1 + ko];
        uint2 A2 = smu[rA2 + ko], A3 = smu[rA3 + ko];
        uint2 B0 = smu[rB0 + ko], B1 = smu[rB1 + ko];
        uint2 B2 = smu[rB2 + ko], B3 = smu[rB3 + ko];
        mma16(acc[0][0], A0.x, A1.x, A0.y, A1.y, B0.x, B0.y);
        mma16(acc[0][1], A0.x, A1.x, A0.y, A1.y, B1.x, B1.y);
        mma16(acc[0][2], A0.x, A1.x, A0.y, A1.y, B2.x, B2.y);
        mma16(acc[0][3], A0.x, A1.x, A0.y, A1.y, B3.x, B3.y);
        mma16(acc[1][0], A2.x, A3.x, A2.y, A3.y, B0.x, B0.y);
        mma16(acc[1][1], A2.x, A3.x, A2.y, A3.y, B1.x, B1.y);
        mma16(acc[1][2], A2.x, A3.x, A2.y, A3.y, B2.x, B2.y);
        mma16(acc[1][3], A2.x, A3.x, A2.y, A3.y, B3.x, B3.y);
    }

    BAR_SYNC(5 + q, 128);   // consumers of quad q done reading its P rows

    float* scr = (float*)(smc + q * 17408);   // quad's dead P region
    if (kh == 1) {
        int id = (w >> 2) - 2;
        float* dst = scr + id * 1024 + lane;
#pragma unroll
        for (int i = 0; i < 2; i++)
#pragma unroll
            for (int j = 0; j < 4; j++)
#pragma unroll
                for (int c = 0; c < 4; c++)
                    dst[((i * 4 + j) * 4 + c) * 32] = acc[i][j][c];
    }
    BAR_SYNC(5 + q, 128);

    if (kh == 0) {
        int id = w >> 2;
        const float* src = scr + id * 1024 + lane;
#pragma unroll
        for (int i = 0; i < 2; i++)
#pragma unroll
            for (int j = 0; j < 4; j++)
#pragma unroll
                for (int c = 0; c < 4; c++)
                    acc[i][j][c] += src[((i * 4 + j) * 4 + c) * 32];

        // Av write: rows t = 4q+2mt+rh, h = g; half2 (d, d+1)
#pragma unroll
        for (int mt = 0; mt < 2; mt++) {
#pragma unroll
            for (int rh = 0; rh < 2; rh++) {
                int tl = 4 * q + 2 * mt + rh;
                float inv = invsm[tl * 8 + g];
                int baseH = AV_H + tl * 640 + 16 * (tl & 3) + 68 * g;
#pragma unroll
                for (int nt = 0; nt < 4; nt++) {
                    int blk = (n0 + 8 * nt) >> 4;
                    int pos = blk * 16 + 4 * s4 + 2 * (nt & 1);
                    __half2 v = __floats2half2_rn(acc[mt][nt][2 * rh] * inv,
                                                  acc[mt][nt][2 * rh + 1] * inv);
                    *(__half2*)(smh + baseH + pos) = v;
                }
            }
        }
    }
    __syncthreads();   // all Av ready

    // ---- MMA2: Out[16 t][64 o] = Av @ Wt^T + b.  n-split 8 x k-split 2. ----
    int ni = w & 7;
    int kh2 = w >> 3;
    int n0b = ni * 8;

    float acc2[4] = {0.f, 0.f, 0.f, 0.f};
    int aR0 = (AV_H >> 2) + g * 160 + (g & 3) * 4 + s4;
    int aR1 = (AV_H >> 2) + (g + 8) * 160 + (g & 3) * 4 + s4;   // (g+8)&3 == g&3
    const uint2* wp = (const uint2*)(g_Wt16 + (size_t)f * DOUT * NK + (size_t)(n0b + g) * NK);
#pragma unroll
    for (int kc = kh2 * 4; kc < kh2 * 4 + 4; kc++) {
#pragma unroll
        for (int k8 = 0; k8 < 4; k8++) {
            uint2 A02 = smu[aR0 + kc * 17 + k8 * 4];
            uint2 A13 = smu[aR1 + kc * 17 + k8 * 4];
            uint2 B01 = __ldg(&wp[kc * 16 + k8 * 4 + s4]);
            mma16(acc2, A02.x, A13.x, A02.y, A13.y, B01.x, B01.y);
        }
    }
    __syncthreads();   // Xt dead -> red
    if (kh2 == 1) {
        float* r = red + (ni * 32 + lane) * 4;
        r[0] = acc2[0]; r[1] = acc2[1]; r[2] = acc2[2]; r[3] = acc2[3];
    }
    __syncthreads();
    if (kh2 == 0) {
        const float* r = red + (ni * 32 + lane) * 4;
        acc2[0] += r[0]; acc2[1] += r[1]; acc2[2] += r[2]; acc2[3] += r[3];

        int tA2 = t0 + g, tB2 = tA2 + 8;
        int oc = n0b + 2 * s4;
        float2 ba = __ldg((const float2*)(Bv + ((size_t)(f * NT + tA2)) * DOUT + oc));
        float2 bb = __ldg((const float2*)(Bv + ((size_t)(f * NT + tB2)) * DOUT + oc));
        *(float2*)(Out + ((size_t)(bf * NT + tA2)) * DOUT + oc) =
            make_float2(acc2[0] + ba.x, acc2[1] + ba.y);
        *(float2*)(Out + ((size_t)(bf * NT + tB2)) * DOUT + oc) =
            make_float2(acc2[2] + bb.x, acc2[3] + bb.y);
    }
}

// ---------------------------------------------------------------------------
extern "C" void kernel_launch(void* const* d_in, const int* in_sizes, int n_in,
                              void* d_out, int out_size)
{
    const float* X     = (const float*)d_in[0];
    const float* ac    = (const float*)d_in[1];
    const float* alpha = (const float*)d_in[2];
    const float* Wq    = (const float*)d_in[3];
    const float* Wk    = (const float*)d_in[4];
    const float* wkey  = (const float*)d_in[5];
    const float* u     = (const float*)d_in[6];
    const float* W     = (const float*)d_in[7];
    const float* Bv    = (const float*)d_in[8];
    float* Out = (float*)d_out;

    cudaFuncSetAttribute(attn_kernel, cudaFuncAttributeMaxDynamicSharedMemorySize, SMEM_BYTES);

    pre_kernel<<<QK_BLOCKS + XT_BLOCKS + WT_BLOCKS, 256, 64 * 65 * 4>>>(X, Wq, Wk, W);
    attn_kernel<<<BF * 16, 512, SMEM_BYTES>>>(ac, alpha, wkey, u, Bv, Out);
}

// round 17
// speedup vs baseline: 1.5569x; 1.0006x over previous
#include <cuda_runtime.h>
#include <cuda_fp16.h>
#include <cstdint>
#include <cstddef>

#define BS 4
#define NF 8
#define NT 256
#define DIN 64
#define NH 8
#define DOUT 64
#define BF (BS*NF)          // 32
#define NK (NH*DIN)         // 512

// Scratch (allocation-free)
__device__ float g_Q[BF * NT * NH * 2];               // [bf][t][h][e]
__device__ float g_K[BF * NT * NH * 2];
__device__ float4 g_K2[BF * 4 * NT];                  // [bf][hp][l]
__device__ __half g_Xt16[(size_t)BF * DIN * NT];      // [bf][d][phys16(l)]
__device__ __half g_Wt16[(size_t)NF * DOUT * NK];     // [f][o][phys16(k)]

static __device__ __forceinline__ uint32_t smem_u32(const void* p) {
    uint32_t a;
    asm("{ .reg .u64 t; cvta.to.shared.u64 t, %1; cvt.u32.u64 %0, t; }" : "=r"(a) : "l"(p));
    return a;
}
#define CP_ASYNC16(dst, src) \
    asm volatile("cp.async.cg.shared.global [%0], [%1], 16;" :: "r"(dst), "l"(src) : "memory")
#define CP_COMMIT()  asm volatile("cp.async.commit_group;" ::: "memory")
#define CP_WAIT0()   asm volatile("cp.async.wait_group 0;" ::: "memory")
#define BAR_ARRIVE(id, n) asm volatile("bar.arrive %0, %1;" :: "r"(id), "r"(n) : "memory")
#define BAR_SYNC(id, n)   asm volatile("bar.sync %0, %1;"   :: "r"(id), "r"(n) : "memory")

// m16n8k16 fp16 MMA, fp32 accum
static __device__ __forceinline__ void mma16(float* d, unsigned a0, unsigned a1,
                                             unsigned a2, unsigned a3,
                                             unsigned b0, unsigned b1) {
    asm volatile("mma.sync.aligned.m16n8k16.row.col.f32.f16.f16.f32 "
        "{%0,%1,%2,%3}, {%4,%5,%6,%7}, {%8,%9}, {%0,%1,%2,%3};"
        : "+f"(d[0]), "+f"(d[1]), "+f"(d[2]), "+f"(d[3])
        : "r"(a0), "r"(a1), "r"(a2), "r"(a3), "r"(b0), "r"(b1));
}

static __device__ __forceinline__ float warp_max_f32(float x) {
    unsigned b = __float_as_uint(x);
    unsigned e = b ^ (unsigned)(((int)b >> 31) | 0x80000000);
    unsigned r;
    asm volatile("redux.sync.max.u32 %0, %1, 0xffffffff;" : "=r"(r) : "r"(e));
    unsigned bb = ((int)r < 0) ? (r ^ 0x80000000u) : ~r;
    return __uint_as_float(bb);
}

// phys16 slot of halfword k within its 16-block: pairs (2m,2m+1) -> slots
// [0,1,8,9, 2,3,10,11, 4,5,12,13, 6,7,14,15]
static __device__ __forceinline__ int slot16(int m) {   // m = (k>>1)&7
    return 4 * (m & 3) + 2 * (m >> 2);
}

// ---------------------------------------------------------------------------
// pre-kernel: [0,1024) QK (+g_K2); [1024,1152) X->Xt16; [1152,1216) W->Wt16.
// ---------------------------------------------------------------------------
#define QK_BLOCKS 1024
#define XT_BLOCKS 128
#define WT_BLOCKS 64

__global__ void __launch_bounds__(256)
pre_kernel(const float* __restrict__ X,
           const float* __restrict__ Wq,
           const float* __restrict__ Wk,
           const float* __restrict__ W)
{
    extern __shared__ float tsm[];   // [64][65]
    int tid = threadIdx.x;

    if (blockIdx.x < QK_BLOCKS) {
        int idx  = blockIdx.x * 8 + (tid >> 5);
        int lane = tid & 31;
        int t_ft = idx & (NF * NT - 1);

        const float* x = X + (size_t)idx * DIN;
        float x0 = __ldg(&x[lane]);
        float x1 = __ldg(&x[lane + 32]);

        int dq = lane >> 2;
        const float4* Wq4 = (const float4*)(Wq + (size_t)t_ft * (DIN * 16));
        const float4* Wk4 = (const float4*)(Wk + (size_t)t_ft * (DIN * 16));

        float4 wq[8], wk[8];
#pragma unroll
        for (int i = 0; i < 8; i++) {
            wq[i] = __ldg(&Wq4[i * 32 + lane]);
            wk[i] = __ldg(&Wk4[i * 32 + lane]);
        }
        float4 aq = {0,0,0,0}, ak = {0,0,0,0};
#pragma unroll
        for (int i = 0; i < 8; i++) {
            int dsel = (i & 3) * 8 + dq;
            float xv = __shfl_sync(0xffffffffu, (i < 4) ? x0 : x1, dsel);
            aq.x = fmaf(xv, wq[i].x, aq.x); aq.y = fmaf(xv, wq[i].y, aq.y);
            aq.z = fmaf(xv, wq[i].z, aq.z); aq.w = fmaf(xv, wq[i].w, aq.w);
            ak.x = fmaf(xv, wk[i].x, ak.x); ak.y = fmaf(xv, wk[i].y, ak.y);
            ak.z = fmaf(xv, wk[i].z, ak.z); ak.w = fmaf(xv, wk[i].w, ak.w);
        }
#pragma unroll
        for (int off = 16; off >= 4; off >>= 1) {
            aq.x += __shfl_xor_sync(0xffffffffu, aq.x, off);
            aq.y += __shfl_xor_sync(0xffffffffu, aq.y, off);
            aq.z += __shfl_xor_sync(0xffffffffu, aq.z, off);
            aq.w += __shfl_xor_sync(0xffffffffu, aq.w, off);
            ak.x += __shfl_xor_sync(0xffffffffu, ak.x, off);
            ak.y += __shfl_xor_sync(0xffffffffu, ak.y, off);
            ak.z += __shfl_xor_sync(0xffffffffu, ak.z, off);
            ak.w += __shfl_xor_sync(0xffffffffu, ak.w, off);
        }
        if (lane < 4) {
            *(float4*)(g_Q + (size_t)idx * 16 + lane * 4) = aq;
        } else if (lane < 8) {
            *(float4*)(g_K + (size_t)idx * 16 + (lane - 4) * 4) = ak;
            int hp = lane - 4;
            g_K2[((size_t)(idx >> 8) * 4 + hp) * NT + (idx & 255)] = ak;
        }
    }
    else if (blockIdx.x < QK_BLOCKS + XT_BLOCKS) {
        // X[bf][lc*64+r][d] -> g_Xt16[bf][d][lc*64 + phys16(r)]
        int b  = blockIdx.x - QK_BLOCKS;
        int bf = b >> 2, lc = b & 3;
        const float4* src = (const float4*)(X + ((size_t)bf * NT + lc * 64) * DIN);
        for (int i = tid; i < 64 * 16; i += 256) {
            int r = i >> 4, c0 = (i & 15) * 4;
            float4 v = __ldg(&src[i]);
            tsm[r * 65 + c0 + 0] = v.x;
            tsm[r * 65 + c0 + 1] = v.y;
            tsm[r * 65 + c0 + 2] = v.z;
            tsm[r * 65 + c0 + 3] = v.w;
        }
        __syncthreads();
        __half* dst = g_Xt16 + (size_t)bf * (DIN * NT) + lc * 64;
        for (int i = tid; i < 64 * 32; i += 256) {
            int d = i >> 5, p = i & 31;
            int la = 2 * p, lb = la + 1;
            int blk = p >> 3, m = p & 7;
            __half2 v = __floats2half2_rn(tsm[la * 65 + d], tsm[lb * 65 + d]);
            *(__half2*)(dst + (size_t)d * NT + blk * 16 + slot16(m)) = v;
        }
    }
    else {
        // W[f][kc*64+r][o] -> g_Wt16[f][o][kc*64 + phys16(r)]
        int b  = blockIdx.x - QK_BLOCKS - XT_BLOCKS;
        int f = b >> 3, kc = b & 7;
        const float4* src = (const float4*)(W + ((size_t)f * NK + kc * 64) * DOUT);
        for (int i = tid; i < 64 * 16; i += 256) {
            int r = i >> 4, c0 = (i & 15) * 4;
            float4 v = __ldg(&src[i]);
            tsm[r * 65 + c0 + 0] = v.x;
            tsm[r * 65 + c0 + 1] = v.y;
            tsm[r * 65 + c0 + 2] = v.z;
            tsm[r * 65 + c0 + 3] = v.w;
        }
        __syncthreads();
        __half* dst = g_Wt16 + (size_t)f * (DOUT * NK) + kc * 64;
        for (int i = tid; i < 64 * 32; i += 256) {
            int o = i >> 5, p = i & 31;
            int ka = 2 * p, kb = ka + 1;
            int blk = p >> 3, m = p & 7;
            __half2 v = __floats2half2_rn(tsm[ka * 65 + o], tsm[kb * 65 + o]);
            *(__half2*)(dst + (size_t)o * NK + blk * 16 + slot16(m)) = v;
        }
    }
}

// ---------------------------------------------------------------------------
// FUSED attn (fp16 MMA path).  grid = BF*16, 512 threads.
// smem (halfwords unless noted):
//   P   [128][272]   @H 0        (69632 B)
//   Xt  [64][272]    @H 34816    (34816 B)
//   Av  16 rows, row t @ H 52224 + t*640 + 16*(t&3), h-chunk stride 68
//   invsm [128] floats @ byte 124928;  total 125440 B
// Exchange scratch overlays quad's P region; red overlays Xt.
// ---------------------------------------------------------------------------
#define SPH 272
#define XT_H 34816
#define AV_H 52224
#define SMEM_BYTES 125440

__global__ void __launch_bounds__(512, 1)
attn_kernel(const float* __restrict__ ac,
            const float* __restrict__ alpha,
            const float* __restrict__ wkey,
            const float* __restrict__ u,
            const float* __restrict__ Bv,
            float* __restrict__ Out)
{
    extern __shared__ float sm[];
    char* smc = (char*)sm;
    __half* smh = (__half*)sm;
    float* invsm = (float*)(smc + 124928);
    float* red = (float*)(smc + 69632);     // overlays Xt (post MMA2 compute)

    int bf   = blockIdx.x >> 4;
    int f    = bf & (NF - 1);
    int t0   = (blockIdx.x & 15) << 4;
    int tid  = threadIdx.x;
    int lane = tid & 31;
    int w    = tid >> 5;
    uint32_t smb = smem_u32(sm);

    // ---- cp.async Xt16 (lands during softmax hp=0) ----
    {
        const __half* Xg = g_Xt16 + (size_t)bf * DIN * NT;
#pragma unroll
        for (int c = 0; c < 4; c++) {
            int i = tid + c * 512;               // 2048 chunks of 16B
            int d = i >> 5, ch = i & 31;
            uint32_t dst = smb + (uint32_t)(69632 + d * 544 + ch * 16);
            CP_ASYNC16(dst, Xg + (size_t)d * NT + ch * 8);
        }
        CP_COMMIT();
    }

    int t     = t0 + w;
    int idx_t = bf * NT + t;
    float alpha_f = __ldg(&alpha[f]);
    float a0c = __ldg(&wkey[f*4+0]), b0c = __ldg(&wkey[f*4+1]);
    float a1c = __ldg(&wkey[f*4+2]), b1c = __ldg(&wkey[f*4+3]);
    float v0 = -alpha_f;
    float rbase = (float)(lane - t);
    const float* uf = u + (size_t)f * (NT * 2);

    // ---- scores + softmax (fp32; raw exp stored as fp16 pairs) ----
#pragma unroll
    for (int hp = 0; hp < 4; hp++) {
        int h0 = hp * 2;
        float4 q4 = __ldg((const float4*)(g_Q + (size_t)idx_t * 16 + h0 * 2));
        float4 k4 = __ldg((const float4*)(g_K + (size_t)idx_t * 16 + h0 * 2));
        float v1a = 2.0f * alpha_f * __ldg(&ac[f * NH + h0]);
        float v1b = 2.0f * alpha_f * __ldg(&ac[f * NH + h0 + 1]);
        float qa0 = q4.x + v0, qa1 = q4.y + v1a;
        float A0 = fmaf(qa0, a0c, qa1 * a1c), B0 = fmaf(qa0, b0c, qa1 * b1c);
        float qb0 = q4.z + v0, qb1 = q4.w + v1b;
        float A1 = fmaf(qb0, a0c, qb1 * a1c), B1 = fmaf(qb0, b0c, qb1 * b1c);

        const float4* Kh = g_K2 + ((size_t)bf * 4 + hp) * NT;
        float4 kv[8];
        float2 uv[8];
#pragma unroll
        for (int j = 0; j < 8; j++) {
            kv[j] = __ldg(&Kh[j * 32 + lane]);
            uv[j] = __ldg((const float2*)(uf + (j * 32 + lane) * 2));
        }

        float s0[8], s1[8], m0 = -3.4e38f, m1 = -3.4e38f;
#pragma unroll
        for (int j = 0; j < 8; j++) {
            float r = rbase + 32.0f * j;
            float ut0 = fmaf(uv[j].x, k4.x, uv[j].y * k4.y);
            float ut1 = fmaf(uv[j].x, k4.z, uv[j].y * k4.w);
            float base0 = fmaf(r, fmaf(A0, r, B0), ut0);
            float base1 = fmaf(r, fmaf(A1, r, B1), ut1);
            base0 = fmaf(q4.x, kv[j].x, base0); base0 = fmaf(q4.y, kv[j].y, base0);
            base1 = fmaf(q4.z, kv[j].z, base1); base1 = fmaf(q4.w, kv[j].w, base1);
            s0[j] = base0; s1[j] = base1;
            m0 = fmaxf(m0, base0); m1 = fmaxf(m1, base1);
        }
        m0 = warp_max_f32(m0);
        m1 = warp_max_f32(m1);

        int rowH0 = (8 * w + h0) * SPH;
        float sum0 = 0.f, sum1 = 0.f;
#pragma unroll
        for (int j = 0; j < 8; j++) {
            float e0 = __expf(s0[j] - m0);
            float e1 = __expf(s1[j] - m1);
            sum0 += e0; sum1 += e1;
            float e0n = __shfl_down_sync(0xffffffffu, e0, 1);
            float e1n = __shfl_down_sync(0xffffffffu, e1, 1);
            if (!(lane & 1)) {
                int l = j * 32 + lane;
                int m = (l >> 1) & 7;
                int pos = ((l >> 4) << 4) + slot16(m);
                *(__half2*)(smh + rowH0 + pos)       = __floats2half2_rn(e0, e0n);
                *(__half2*)(smh + rowH0 + SPH + pos) = __floats2half2_rn(e1, e1n);
            }
        }
#pragma unroll
        for (int o = 16; o; o >>= 1) {
            sum0 += __shfl_xor_sync(0xffffffffu, sum0, o);
            sum1 += __shfl_xor_sync(0xffffffffu, sum1, o);
        }
        if (lane == 0) {
            invsm[8 * w + h0]     = 1.0f / sum0;
            invsm[8 * w + h0 + 1] = 1.0f / sum1;
        }
        if (hp == 0) {
            CP_WAIT0();
            __syncthreads();
        }
    }

    BAR_ARRIVE(1 + (w >> 2), 256);
    BAR_SYNC(1 + (w & 3), 256);

    // ---- MMA1: warp = (q m32) x (nh n32) x (kh k128).  LDS.64 fragments. ----
    int g  = lane >> 2;
    int s4 = lane & 3;
    int q  = w & 3;
    int nh = (w >> 2) & 1;
    int kh = w >> 3;
    int n0 = nh * 32;

    const uint2* smu = (const uint2*)sm;   // idx = halfword/4
    int ko0 = kh * 32;                     // kh*128 halfwords /4
    int rA0 = (32 * q + g) * 68 + s4 + ko0;
    int rA1 = rA0 + 8 * 68;
    int rA2 = rA0 + 16 * 68;
    int rA3 = rA0 + 24 * 68;
    int rB0 = 8704 + (n0 + g) * 68 + s4 + ko0;
    int rB1 = rB0 + 8 * 68;
    int rB2 = rB0 + 16 * 68;
    int rB3 = rB0 + 24 * 68;

    float acc[2][4][4];
#pragma unroll
    for (int i = 0; i < 2; i++)
#pragma unroll
        for (int j = 0; j < 4; j++)
#pragma unroll
            for (int c = 0; c < 4; c++) acc[i][j][c] = 0.f;

#pragma unroll
    for (int st = 0; st < 8; st++) {
        int ko = st * 4;
        uint2 A0 = smu[rA0 + ko], A1 = smu[rA1 + ko];
        uint2 A2 = smu[rA2 + ko], A3 = smu[rA3 + ko];
        uint2 B0 = smu[rB0 + ko], B1 = smu[rB1 + ko];
        uint2 B2 = smu[rB2 + ko], B3 = smu[rB3 + ko];
        mma16(acc[0][0], A0.x, A1.x, A0.y, A1.y, B0.x, B0.y);
        mma16(acc[0][1], A0.x, A1.x, A0.y, A1.y, B1.x, B1.y);
        mma16(acc[0][2], A0.x, A1.x, A0.y, A1.y, B2.x, B2.y);
        mma16(acc[0][3], A0.x, A1.x, A0.y, A1.y, B3.x, B3.y);
        mma16(acc[1][0], A2.x, A3.x, A2.y, A3.y, B0.x, B0.y);
        mma16(acc[1][1], A2.x, A3.x, A2.y, A3.y, B1.x, B1.y);
        mma16(acc[1][2], A2.x, A3.x, A2.y, A3.y, B2.x, B2.y);
        mma16(acc[1][3], A2.x, A3.x, A2.y, A3.y, B3.x, B3.y);
    }

    BAR_SYNC(5 + q, 128);   // consumers of quad q done reading its P rows

    float* scr = (float*)(smc + q * 17408);   // quad's dead P region
    if (kh == 1) {
        int id = (w >> 2) - 2;
        float* dst = scr + id * 1024 + lane;
#pragma unroll
        for (int i = 0; i < 2; i++)
#pragma unroll
            for (int j = 0; j < 4; j++)
#pragma unroll
                for (int c = 0; c < 4; c++)
                    dst[((i * 4 + j) * 4 + c) * 32] = acc[i][j][c];
    }
    BAR_SYNC(5 + q, 128);

    if (kh == 0) {
        int id = w >> 2;
        const float* src = scr + id * 1024 + lane;
#pragma unroll
        for (int i = 0; i < 2; i++)
#pragma unroll
            for (int j = 0; j < 4; j++)
#pragma unroll
                for (int c = 0; c < 4; c++)
                    acc[i][j][c] += src[((i * 4 + j) * 4 + c) * 32];

        // Av write: rows t = 4q+2mt+rh, h = g; half2 (d, d+1)
#pragma unroll
        for (int mt = 0; mt < 2; mt++) {
#pragma unroll
            for (int rh = 0; rh < 2; rh++) {
                int tl = 4 * q + 2 * mt + rh;
                float inv = invsm[tl * 8 + g];
                int baseH = AV_H + tl * 640 + 16 * (tl & 3) + 68 * g;
#pragma unroll
                for (int nt = 0; nt < 4; nt++) {
                    int blk = (n0 + 8 * nt) >> 4;
                    int pos = blk * 16 + 4 * s4 + 2 * (nt & 1);
                    __half2 v = __floats2half2_rn(acc[mt][nt][2 * rh] * inv,
                                                  acc[mt][nt][2 * rh + 1] * inv);
                    *(__half2*)(smh + baseH + pos) = v;
                }
            }
        }
    }
    __syncthreads();   // all Av ready

    // ---- MMA2: Out[16 t][64 o] = Av @ Wt^T + b.  n-split 8 x k-split 2. ----
    int ni = w & 7;
    int kh2 = w >> 3;
    int n0b = ni * 8;

    float acc2[4] = {0.f, 0.f, 0.f, 0.f};
    int aR0 = (AV_H >> 2) + g * 160 + (g & 3) * 4 + s4;
    int aR1 = (AV_H >> 2) + (g + 8) * 160 + (g & 3) * 4 + s4;   // (g+8)&3 == g&3
    const uint2* wp = (const uint2*)(g_Wt16 + (size_t)f * DOUT * NK + (size_t)(n0b + g) * NK);
#pragma unroll
    for (int kc = kh2 * 4; kc < kh2 * 4 + 4; kc++) {
#pragma unroll
        for (int k8 = 0; k8 < 4; k8++) {
            uint2 A02 = smu[aR0 + kc * 17 + k8 * 4];
            uint2 A13 = smu[aR1 + kc * 17 + k8 * 4];
            uint2 B01 = __ldg(&wp[kc * 16 + k8 * 4 + s4]);
            mma16(acc2, A02.x, A13.x, A02.y, A13.y, B01.x, B01.y);
        }
    }
    __syncthreads();   // Xt dead -> red
    if (kh2 == 1) {
        float* r = red + (ni * 32 + lane) * 4;
        r[0] = acc2[0]; r[1] = acc2[1]; r[2] = acc2[2]; r[3] = acc2[3];
    }
    __syncthreads();
    if (kh2 == 0) {
        const float* r = red + (ni * 32 + lane) * 4;
        acc2[0] += r[0]; acc2[1] += r[1]; acc2[2] += r[2]; acc2[3] += r[3];

        int tA2 = t0 + g, tB2 = tA2 + 8;
        int oc = n0b + 2 * s4;
        float2 ba = __ldg((const float2*)(Bv + ((size_t)(f * NT + tA2)) * DOUT + oc));
        float2 bb = __ldg((const float2*)(Bv + ((size_t)(f * NT + tB2)) * DOUT + oc));
        *(float2*)(Out + ((size_t)(bf * NT + tA2)) * DOUT + oc) =
            make_float2(acc2[0] + ba.x, acc2[1] + ba.y);
        *(float2*)(Out + ((size_t)(bf * NT + tB2)) * DOUT + oc) =
            make_float2(acc2[2] + bb.x, acc2[3] + bb.y);
    }
}

// ---------------------------------------------------------------------------
extern "C" void kernel_launch(void* const* d_in, const int* in_sizes, int n_in,
                              void* d_out, int out_size)
{
    const float* X     = (const float*)d_in[0];
    const float* ac    = (const float*)d_in[1];
    const float* alpha = (const float*)d_in[2];
    const float* Wq    = (const float*)d_in[3];
    const float* Wk    = (const float*)d_in[4];
    const float* wkey  = (const float*)d_in[5];
    const float* u     = (const float*)d_in[6];
    const float* W     = (const float*)d_in[7];
    const float* Bv    = (const float*)d_in[8];
    float* Out = (float*)d_out;

    cudaFuncSetAttribute(attn_kernel, cudaFuncAttributeMaxDynamicSharedMemorySize, SMEM_BYTES);

    pre_kernel<<<QK_BLOCKS + XT_BLOCKS + WT_BLOCKS, 256, 64 * 65 * 4>>>(X, Wq, Wk, W);
    attn_kernel<<<BF * 16, 512, SMEM_BYTES>>>(ac, alpha, wkey, u, Bv, Out);
}